// round 5
// baseline (speedup 1.0000x reference)
#include <cuda_runtime.h>
#include <math.h>
#include <cstdint>

#define NTOK 8192
#define CDIM 1024
#define HDIM 128

// Scratch (__device__ globals; allocation-free rule)
__device__ float g_q [(size_t)NTOK * HDIM];
__device__ float g_k [(size_t)NTOK * HDIM];
__device__ float g_vT[(size_t)CDIM * NTOK];   // v transposed: [C, N]
__device__ float g_s [(size_t)NTOK * NTOK];   // 256 MB scores
__device__ float g_o [(size_t)NTOK * CDIM];
__device__ float g_xr[(size_t)NTOK * CDIM];   // tf32-rounded x
__device__ float g_wq[(size_t)HDIM * CDIM];
__device__ float g_wk[(size_t)HDIM * CDIM];
__device__ float g_wv[(size_t)CDIM * CDIM];
__device__ float g_wo[(size_t)CDIM * CDIM];

// ---------------- portable PTX helpers (sm_80-level only) ----------------
__device__ __forceinline__ uint32_t smem_u32(const void* p) {
    uint32_t a;
    asm("{ .reg .u64 t; cvta.to.shared.u64 t, %1; cvt.u32.u64 %0, t; }"
        : "=r"(a) : "l"(p));
    return a;
}
__device__ __forceinline__ void cp16(uint32_t s, const void* g) {
    asm volatile("cp.async.cg.shared.global [%0], [%1], 16;" :: "r"(s), "l"(g));
}
__device__ __forceinline__ float rtf(float x) {   // round-to-nearest tf32
    uint32_t u;
    asm("cvt.rna.tf32.f32 %0, %1;" : "=r"(u) : "f"(x));
    return __uint_as_float(u);
}
__device__ __forceinline__ void ldsm4(uint32_t& r0, uint32_t& r1,
                                      uint32_t& r2, uint32_t& r3, uint32_t a) {
    asm volatile("ldmatrix.sync.aligned.m8n8.x4.shared.b16 {%0,%1,%2,%3}, [%4];"
                 : "=r"(r0), "=r"(r1), "=r"(r2), "=r"(r3) : "r"(a));
}
__device__ __forceinline__ void mma8(float* c, const uint32_t* a, const uint32_t* b) {
    asm volatile(
        "mma.sync.aligned.m16n8k8.row.col.f32.tf32.tf32.f32 "
        "{%0,%1,%2,%3}, {%4,%5,%6,%7}, {%8,%9}, {%0,%1,%2,%3};"
        : "+f"(c[0]), "+f"(c[1]), "+f"(c[2]), "+f"(c[3])
        : "r"(a[0]), "r"(a[1]), "r"(a[2]), "r"(a[3]), "r"(b[0]), "r"(b[1]));
}

// ---------------------------------------------------------------------------
__global__ __launch_bounds__(256)
void round_tf32(const float* __restrict__ src, float* __restrict__ dst, int n4) {
    int i = blockIdx.x * 256 + threadIdx.x;
    if (i < n4) {
        float4 v = reinterpret_cast<const float4*>(src)[i];
        v.x = rtf(v.x); v.y = rtf(v.y); v.z = rtf(v.z); v.w = rtf(v.w);
        reinterpret_cast<float4*>(dst)[i] = v;
    }
}

#define AST 36                       // padded row stride (floats)

// ===========================================================================
// Small GEMM (q/k proj): CTA 128x128, warp 64x32, 2 CTAs/SM, 3-stage.
// C = alpha*A@B^T + bias[n]; operands pre-rounded tf32; output tf32-rounded.
// ===========================================================================
#define TILEB_S (128 * AST * 4)
#define BUFB_S  (2 * TILEB_S)
#define NSTAGE_S 3

__global__ __launch_bounds__(256, 2)
void gemm_s(const float* __restrict__ A, const float* __restrict__ B,
            const float* __restrict__ bias, float* __restrict__ C,
            int M, int Nn, int K) {
    extern __shared__ float sm[];
    const uint32_t sA = smem_u32(sm);
    const uint32_t sB = sA + TILEB_S;

    const int tid = threadIdx.x;
    const int lane = tid & 31, wid = tid >> 5;
    const int wm = wid >> 2, wn = wid & 3;
    const int m0 = blockIdx.y * 128, n0 = blockIdx.x * 128;

    const int q = lane & 7, sub = lane >> 3;
    uint32_t aAddr[4], bAddr[2];
#pragma unroll
    for (int mt = 0; mt < 4; mt++)
        aAddr[mt] = sA + (uint32_t)((wm * 64 + mt * 16 + (sub & 1) * 8 + q) * AST
                                    + (sub >> 1) * 4) * 4;
#pragma unroll
    for (int p = 0; p < 2; p++)
        bAddr[p] = sB + (uint32_t)((wn * 32 + p * 16 + (sub >> 1) * 8 + q) * AST
                                   + (sub & 1) * 4) * 4;

    const int NC = K >> 5;
    auto load = [&](int c, int b) {
        if (c < NC) {
            const uint32_t aBase = sA + (uint32_t)b * BUFB_S;
            const uint32_t bBase = sB + (uint32_t)b * BUFB_S;
#pragma unroll
            for (int it = 0; it < 8; it++) {
                int i = tid + it * 256;
                bool isA = i < 1024;
                int idx = i & 1023;
                int rr = idx >> 3, cc = idx & 7;
                const float* g = (isA ? A : B) +
                    (size_t)((isA ? m0 : n0) + rr) * K + c * 32 + cc * 4;
                cp16((isA ? aBase : bBase) + (uint32_t)(rr * AST + cc * 4) * 4, g);
            }
        }
        asm volatile("cp.async.commit_group;" ::: "memory");
    };

    load(0, 0); load(1, 1); load(2, 2);

    float acc[4][4][4];
#pragma unroll
    for (int i = 0; i < 4; i++)
#pragma unroll
        for (int j = 0; j < 4; j++)
#pragma unroll
            for (int r = 0; r < 4; r++) acc[i][j][r] = 0.f;

    for (int c = 0; c < NC; c++) {
        asm volatile("cp.async.wait_group %0;" :: "n"(NSTAGE_S - 1) : "memory");
        __syncthreads();
        const uint32_t boff = (uint32_t)(c % NSTAGE_S) * BUFB_S;
#pragma unroll
        for (int ks = 0; ks < 4; ks++) {
            uint32_t af[4][4], bf[4][2];
#pragma unroll
            for (int mt = 0; mt < 4; mt++)
                ldsm4(af[mt][0], af[mt][1], af[mt][2], af[mt][3],
                      aAddr[mt] + boff + ks * 32);
#pragma unroll
            for (int p = 0; p < 2; p++) {
                uint32_t r0, r1, r2, r3;
                ldsm4(r0, r1, r2, r3, bAddr[p] + boff + ks * 32);
                bf[p * 2][0] = r0; bf[p * 2][1] = r1;
                bf[p * 2 + 1][0] = r2; bf[p * 2 + 1][1] = r3;
            }
#pragma unroll
            for (int mt = 0; mt < 4; mt++)
#pragma unroll
                for (int nt = 0; nt < 4; nt++)
                    mma8(acc[mt][nt], af[mt], bf[nt]);
        }
        __syncthreads();
        load(c + NSTAGE_S, c % NSTAGE_S);
    }

    const int g = lane >> 2, tig = lane & 3;
#pragma unroll
    for (int mt = 0; mt < 4; mt++) {
        const int mrow = m0 + wm * 64 + mt * 16 + g;
#pragma unroll
        for (int nt = 0; nt < 4; nt++) {
            const int ncol = n0 + wn * 32 + nt * 8 + tig * 2;
            float* cc = acc[mt][nt];
            float b0 = bias[ncol], b1 = bias[ncol + 1];
            float2 v0, v1;
            v0.x = rtf(cc[0] + b0); v0.y = rtf(cc[1] + b1);
            v1.x = rtf(cc[2] + b0); v1.y = rtf(cc[3] + b1);
            *reinterpret_cast<float2*>(&C[(size_t)mrow * Nn + ncol]) = v0;
            *reinterpret_cast<float2*>(&C[(size_t)(mrow + 8) * Nn + ncol]) = v1;
        }
    }
}

// ===========================================================================
// Big GEMM: CTA 128x256, 8 warps as 2(M)x4(N), warp tile 64x64, 1 CTA/SM,
// 3-stage cp.async (162 KB smem). 16.4 FLOP per smem byte.
//   BIAS: 0 none, 1 bias[n], 2 bias[m].  ROUND: tf32-round output.
// ===========================================================================
#define ATILE_B (128 * AST * 4)      // 18432
#define BTILE_B (256 * AST * 4)      // 36864
#define BUFB_B  (ATILE_B + BTILE_B)  // 55296
#define NSTAGE_B 3

template <int BIAS, int ROUND>
__global__ __launch_bounds__(256, 1)
void gemm_b(const float* __restrict__ A, const float* __restrict__ B,
            const float* __restrict__ bias, float* __restrict__ C,
            int M, int Nn, int K, float alpha) {
    extern __shared__ float sm[];
    const uint32_t sA = smem_u32(sm);
    const uint32_t sB = sA + ATILE_B;

    const int tid = threadIdx.x;
    const int lane = tid & 31, wid = tid >> 5;
    const int wm = wid >> 2, wn = wid & 3;       // 2(M) x 4(N)
    const int m0 = blockIdx.y * 128, n0 = blockIdx.x * 256;

    const int q = lane & 7, sub = lane >> 3;
    uint32_t aAddr[4], bAddr[4];
#pragma unroll
    for (int mt = 0; mt < 4; mt++)
        aAddr[mt] = sA + (uint32_t)((wm * 64 + mt * 16 + (sub & 1) * 8 + q) * AST
                                    + (sub >> 1) * 4) * 4;
#pragma unroll
    for (int p = 0; p < 4; p++)
        bAddr[p] = sB + (uint32_t)((wn * 64 + p * 16 + (sub >> 1) * 8 + q) * AST
                                   + (sub & 1) * 4) * 4;

    const int NC = K >> 5;
    auto load = [&](int c, int b) {
        if (c < NC) {
            const uint32_t aBase = sA + (uint32_t)b * BUFB_B;
            const uint32_t bBase = sB + (uint32_t)b * BUFB_B;
#pragma unroll
            for (int it = 0; it < 12; it++) {
                int i = tid + it * 256;              // 0..3071
                bool isA = i < 1024;
                int idx = isA ? i : i - 1024;        // A: 1024, B: 2048
                int rr = idx >> 3, cc = idx & 7;
                const float* g = (isA ? A : B) +
                    (size_t)((isA ? m0 : n0) + rr) * K + c * 32 + cc * 4;
                cp16((isA ? aBase : bBase) + (uint32_t)(rr * AST + cc * 4) * 4, g);
            }
        }
        asm volatile("cp.async.commit_group;" ::: "memory");
    };

    load(0, 0); load(1, 1); load(2, 2);

    float acc[4][8][4];
#pragma unroll
    for (int i = 0; i < 4; i++)
#pragma unroll
        for (int j = 0; j < 8; j++)
#pragma unroll
            for (int r = 0; r < 4; r++) acc[i][j][r] = 0.f;

    for (int c = 0; c < NC; c++) {
        asm volatile("cp.async.wait_group %0;" :: "n"(NSTAGE_B - 1) : "memory");
        __syncthreads();
        const uint32_t boff = (uint32_t)(c % NSTAGE_B) * BUFB_B;
#pragma unroll
        for (int ks = 0; ks < 4; ks++) {
            uint32_t af[4][4], bf[8][2];
#pragma unroll
            for (int mt = 0; mt < 4; mt++)
                ldsm4(af[mt][0], af[mt][1], af[mt][2], af[mt][3],
                      aAddr[mt] + boff + ks * 32);
#pragma unroll
            for (int p = 0; p < 4; p++) {
                uint32_t r0, r1, r2, r3;
                ldsm4(r0, r1, r2, r3, bAddr[p] + boff + ks * 32);
                bf[p * 2][0] = r0; bf[p * 2][1] = r1;
                bf[p * 2 + 1][0] = r2; bf[p * 2 + 1][1] = r3;
            }
#pragma unroll
            for (int mt = 0; mt < 4; mt++)
#pragma unroll
                for (int nt = 0; nt < 8; nt++)
                    mma8(acc[mt][nt], af[mt], bf[nt]);
        }
        __syncthreads();
        load(c + NSTAGE_B, c % NSTAGE_B);
    }

    // ---- epilogue ----
    const int g = lane >> 2, tig = lane & 3;
#pragma unroll
    for (int mt = 0; mt < 4; mt++) {
        const int mrow = m0 + wm * 64 + mt * 16 + g;
        float bR0 = 0.f, bR1 = 0.f;
        if (BIAS == 2) { bR0 = bias[mrow]; bR1 = bias[mrow + 8]; }
#pragma unroll
        for (int nt = 0; nt < 8; nt++) {
            const int ncol = n0 + wn * 64 + nt * 8 + tig * 2;
            float* cc = acc[mt][nt];
            float2 v0, v1;
            v0.x = cc[0] * alpha; v0.y = cc[1] * alpha;
            v1.x = cc[2] * alpha; v1.y = cc[3] * alpha;
            if (BIAS == 1) {
                float b0 = bias[ncol], b1 = bias[ncol + 1];
                v0.x += b0; v0.y += b1; v1.x += b0; v1.y += b1;
            } else if (BIAS == 2) {
                v0.x += bR0; v0.y += bR0; v1.x += bR1; v1.y += bR1;
            }
            if (ROUND) {
                v0.x = rtf(v0.x); v0.y = rtf(v0.y);
                v1.x = rtf(v1.x); v1.y = rtf(v1.y);
            }
            *reinterpret_cast<float2*>(&C[(size_t)mrow * Nn + ncol]) = v0;
            *reinterpret_cast<float2*>(&C[(size_t)(mrow + 8) * Nn + ncol]) = v1;
        }
    }
}

// ---------------------------------------------------------------------------
// Row softmax (8192-wide), in place, float4-vectorized; output tf32-rounded.
// ---------------------------------------------------------------------------
__global__ __launch_bounds__(256)
void softmax_rows(float* __restrict__ S) {
    const size_t row = blockIdx.x;
    float4* p = reinterpret_cast<float4*>(S + row * NTOK);
    const int tid = threadIdx.x;
    const int lane = tid & 31, wid = tid >> 5;
    __shared__ float red[8];

    float4 v[8];
    float mx = -INFINITY;
#pragma unroll
    for (int i = 0; i < 8; i++) {
        v[i] = p[tid + i * 256];
        mx = fmaxf(mx, fmaxf(fmaxf(v[i].x, v[i].y), fmaxf(v[i].z, v[i].w)));
    }
#pragma unroll
    for (int o = 16; o > 0; o >>= 1) mx = fmaxf(mx, __shfl_xor_sync(~0u, mx, o));
    if (lane == 0) red[wid] = mx;
    __syncthreads();
    mx = red[0];
#pragma unroll
    for (int i = 1; i < 8; i++) mx = fmaxf(mx, red[i]);
    __syncthreads();

    float sum = 0.f;
#pragma unroll
    for (int i = 0; i < 8; i++) {
        v[i].x = __expf(v[i].x - mx); v[i].y = __expf(v[i].y - mx);
        v[i].z = __expf(v[i].z - mx); v[i].w = __expf(v[i].w - mx);
        sum += (v[i].x + v[i].y) + (v[i].z + v[i].w);
    }
#pragma unroll
    for (int o = 16; o > 0; o >>= 1) sum += __shfl_xor_sync(~0u, sum, o);
    if (lane == 0) red[wid] = sum;
    __syncthreads();
    sum = red[0];
#pragma unroll
    for (int i = 1; i < 8; i++) sum += red[i];

    const float inv = 1.f / sum;
#pragma unroll
    for (int i = 0; i < 8; i++) {
        v[i].x = rtf(v[i].x * inv); v[i].y = rtf(v[i].y * inv);
        v[i].z = rtf(v[i].z * inv); v[i].w = rtf(v[i].w * inv);
        p[tid + i * 256] = v[i];
    }
}

// ---------------------------------------------------------------------------
extern "C" void kernel_launch(void* const* d_in, const int* in_sizes, int n_in,
                              void* d_out, int out_size) {
    const float* x  = (const float*)d_in[0];
    const float* Wq = (const float*)d_in[1];
    const float* bq = (const float*)d_in[2];
    const float* Wk = (const float*)d_in[3];
    const float* bk = (const float*)d_in[4];
    const float* Wv = (const float*)d_in[5];
    const float* bv = (const float*)d_in[6];
    const float* Wo = (const float*)d_in[7];
    const float* bo = (const float*)d_in[8];
    float* out = (float*)d_out;

    float *qp, *kp, *vTp, *sp, *op, *xr, *wq, *wk, *wv, *wo;
    cudaGetSymbolAddress((void**)&qp,  g_q);
    cudaGetSymbolAddress((void**)&kp,  g_k);
    cudaGetSymbolAddress((void**)&vTp, g_vT);
    cudaGetSymbolAddress((void**)&sp,  g_s);
    cudaGetSymbolAddress((void**)&op,  g_o);
    cudaGetSymbolAddress((void**)&xr,  g_xr);
    cudaGetSymbolAddress((void**)&wq,  g_wq);
    cudaGetSymbolAddress((void**)&wk,  g_wk);
    cudaGetSymbolAddress((void**)&wv,  g_wv);
    cudaGetSymbolAddress((void**)&wo,  g_wo);

    const float scale = 1.0f / sqrtf((float)HDIM);
    const int SMEM_S = NSTAGE_S * BUFB_S;   // 110592
    const int SMEM_B = NSTAGE_B * BUFB_B;   // 165888

    cudaFuncSetAttribute(gemm_s, cudaFuncAttributeMaxDynamicSharedMemorySize, SMEM_S);
    cudaFuncSetAttribute(gemm_b<2, 1>, cudaFuncAttributeMaxDynamicSharedMemorySize, SMEM_B);
    cudaFuncSetAttribute(gemm_b<0, 0>, cudaFuncAttributeMaxDynamicSharedMemorySize, SMEM_B);
    cudaFuncSetAttribute(gemm_b<0, 1>, cudaFuncAttributeMaxDynamicSharedMemorySize, SMEM_B);
    cudaFuncSetAttribute(gemm_b<1, 0>, cudaFuncAttributeMaxDynamicSharedMemorySize, SMEM_B);

    dim3 blk(256);

    // ---- pre-round all mainloop operand sources to tf32 ----
    round_tf32<<<(NTOK * CDIM / 4 + 255) / 256, blk>>>(x,  xr, NTOK * CDIM / 4);
    round_tf32<<<(HDIM * CDIM / 4 + 255) / 256, blk>>>(Wq, wq, HDIM * CDIM / 4);
    round_tf32<<<(HDIM * CDIM / 4 + 255) / 256, blk>>>(Wk, wk, HDIM * CDIM / 4);
    round_tf32<<<(CDIM * CDIM / 4 + 255) / 256, blk>>>(Wv, wv, CDIM * CDIM / 4);
    round_tf32<<<(CDIM * CDIM / 4 + 255) / 256, blk>>>(Wo, wo, CDIM * CDIM / 4);

    // q = x @ Wq.T + bq ; k = x @ Wk.T + bk  (N=128 -> small kernel)
    gemm_s<<<dim3(1, 64), blk, SMEM_S>>>(xr, wq, bq, qp, NTOK, HDIM, CDIM);
    gemm_s<<<dim3(1, 64), blk, SMEM_S>>>(xr, wk, bk, kp, NTOK, HDIM, CDIM);

    // vT = Wv @ x.T + bv[m] : M=1024, N=8192, K=1024
    gemm_b<2, 1><<<dim3(32, 8), blk, SMEM_B>>>(wv, xr, bv, vTp, CDIM, NTOK, CDIM, 1.0f);

    // scores = (q @ k.T) * scale : M=N=8192, K=128
    gemm_b<0, 0><<<dim3(32, 64), blk, SMEM_B>>>(qp, kp, nullptr, sp, NTOK, NTOK, HDIM, scale);

    softmax_rows<<<NTOK, blk>>>(sp);

    // o = attn @ vT.T : M=8192, N=1024, K=8192
    gemm_b<0, 1><<<dim3(4, 64), blk, SMEM_B>>>(sp, vTp, nullptr, op, NTOK, CDIM, NTOK, 1.0f);

    // out = o @ Wo.T + bo : M=8192, N=1024, K=1024
    gemm_b<1, 0><<<dim3(4, 64), blk, SMEM_B>>>(op, wo, bo, out, NTOK, CDIM, CDIM, 1.0f);
}

// round 7
// speedup vs baseline: 1.0610x; 1.0610x over previous
#include <cuda_runtime.h>
#include <math.h>
#include <cstdint>

#define NTOK 8192
#define CDIM 1024
#define HDIM 128

// Scratch (__device__ globals; allocation-free rule)
__device__ float g_q [(size_t)NTOK * HDIM];
__device__ float g_k [(size_t)NTOK * HDIM];
__device__ float g_vT[(size_t)CDIM * NTOK];   // v transposed: [C, N]
__device__ float g_s [(size_t)NTOK * NTOK];   // 256 MB exp'd scores
__device__ float g_o [(size_t)NTOK * CDIM];
__device__ float g_xr[(size_t)NTOK * CDIM];   // tf32-rounded x
__device__ float g_wq[(size_t)HDIM * CDIM];
__device__ float g_wk[(size_t)HDIM * CDIM];
__device__ float g_wv[(size_t)CDIM * CDIM];
__device__ float g_wo[(size_t)CDIM * CDIM];
__device__ float g_rsum[NTOK];                // softmax row sums

// ---------------- portable PTX helpers (sm_80-level only) ----------------
__device__ __forceinline__ uint32_t smem_u32(const void* p) {
    uint32_t a;
    asm("{ .reg .u64 t; cvta.to.shared.u64 t, %1; cvt.u32.u64 %0, t; }"
        : "=r"(a) : "l"(p));
    return a;
}
__device__ __forceinline__ void cp16(uint32_t s, const void* g) {
    asm volatile("cp.async.cg.shared.global [%0], [%1], 16;" :: "r"(s), "l"(g));
}
__device__ __forceinline__ float rtf(float x) {   // round-to-nearest tf32
    uint32_t u;
    asm("cvt.rna.tf32.f32 %0, %1;" : "=r"(u) : "f"(x));
    return __uint_as_float(u);
}
__device__ __forceinline__ void ldsm4(uint32_t& r0, uint32_t& r1,
                                      uint32_t& r2, uint32_t& r3, uint32_t a) {
    asm volatile("ldmatrix.sync.aligned.m8n8.x4.shared.b16 {%0,%1,%2,%3}, [%4];"
                 : "=r"(r0), "=r"(r1), "=r"(r2), "=r"(r3) : "r"(a));
}
__device__ __forceinline__ void mma8(float* c, const uint32_t* a, const uint32_t* b) {
    asm volatile(
        "mma.sync.aligned.m16n8k8.row.col.f32.tf32.tf32.f32 "
        "{%0,%1,%2,%3}, {%4,%5,%6,%7}, {%8,%9}, {%0,%1,%2,%3};"
        : "+f"(c[0]), "+f"(c[1]), "+f"(c[2]), "+f"(c[3])
        : "r"(a[0]), "r"(a[1]), "r"(a[2]), "r"(a[3]), "r"(b[0]), "r"(b[1]));
}

// ---------------------------------------------------------------------------
__global__ __launch_bounds__(256)
void round_tf32(const float* __restrict__ src, float* __restrict__ dst, int n4) {
    int i = blockIdx.x * 256 + threadIdx.x;
    if (i < n4) {
        float4 v = reinterpret_cast<const float4*>(src)[i];
        v.x = rtf(v.x); v.y = rtf(v.y); v.z = rtf(v.z); v.w = rtf(v.w);
        reinterpret_cast<float4*>(dst)[i] = v;
    }
}

__global__ __launch_bounds__(256)
void zero_rsum(float* __restrict__ r) {
    r[blockIdx.x * 256 + threadIdx.x] = 0.f;
}

// ---------------------------------------------------------------------------
// tf32 tensor-core GEMM (R4 config): C = A @ B^T, CTA 128x128, BK=32,
// 3-stage cp.async, 8 warps 2(M)x4(N), warp tile 64x32, 2 CTAs/SM.
// EPI epilogue modes:
//   0: C = acc                      (plain)
//   1: C = rtf(acc + bias[n])       (projection feeding another GEMM)
//   2: C = rtf(acc + bias[m])       (vT)
//   3: C = rtf(exp(acc*alpha)); atomicAdd row sums     (scores+softmax-exp)
//   4: C = rtf(acc / rsum[m])       (attn@v with deferred normalization)
//   5: C = acc + bias[n]            (final out-proj)
// ---------------------------------------------------------------------------
#define AST 36
#define TILEB (128 * AST * 4)
#define BUFB  (2 * TILEB)
#define NSTAGE 3

template <int EPI>
__global__ __launch_bounds__(256, 2)
void gemm_mma(const float* __restrict__ A, const float* __restrict__ B,
              const float* __restrict__ bias, float* __restrict__ rsum,
              float* __restrict__ C, int M, int Nn, int K, float alpha) {
    extern __shared__ float sm[];
    const uint32_t sA = smem_u32(sm);
    const uint32_t sB = sA + TILEB;

    const int tid = threadIdx.x;
    const int lane = tid & 31, wid = tid >> 5;
    const int wm = wid >> 2, wn = wid & 3;
    const int m0 = blockIdx.y * 128, n0 = blockIdx.x * 128;

    const int q = lane & 7, sub = lane >> 3;
    uint32_t aAddr[4], bAddr[2];
#pragma unroll
    for (int mt = 0; mt < 4; mt++)
        aAddr[mt] = sA + (uint32_t)((wm * 64 + mt * 16 + (sub & 1) * 8 + q) * AST
                                    + (sub >> 1) * 4) * 4;
#pragma unroll
    for (int p = 0; p < 2; p++)
        bAddr[p] = sB + (uint32_t)((wn * 32 + p * 16 + (sub >> 1) * 8 + q) * AST
                                   + (sub & 1) * 4) * 4;

    const int NC = K >> 5;
    auto load = [&](int c, int b) {
        if (c < NC) {
            const uint32_t aBase = sA + (uint32_t)b * BUFB;
            const uint32_t bBase = sB + (uint32_t)b * BUFB;
#pragma unroll
            for (int it = 0; it < 8; it++) {
                int i = tid + it * 256;
                bool isA = i < 1024;
                int idx = i & 1023;
                int rr = idx >> 3, cc = idx & 7;
                const float* g = (isA ? A : B) +
                    (size_t)((isA ? m0 : n0) + rr) * K + c * 32 + cc * 4;
                cp16((isA ? aBase : bBase) + (uint32_t)(rr * AST + cc * 4) * 4, g);
            }
        }
        asm volatile("cp.async.commit_group;" ::: "memory");
    };

    load(0, 0); load(1, 1); load(2, 2);

    float acc[4][4][4];
#pragma unroll
    for (int i = 0; i < 4; i++)
#pragma unroll
        for (int j = 0; j < 4; j++)
#pragma unroll
            for (int r = 0; r < 4; r++) acc[i][j][r] = 0.f;

    for (int c = 0; c < NC; c++) {
        asm volatile("cp.async.wait_group %0;" :: "n"(NSTAGE - 1) : "memory");
        __syncthreads();
        const uint32_t boff = (uint32_t)(c % NSTAGE) * BUFB;
#pragma unroll
        for (int ks = 0; ks < 4; ks++) {
            uint32_t af[4][4], bf[4][2];
#pragma unroll
            for (int mt = 0; mt < 4; mt++)
                ldsm4(af[mt][0], af[mt][1], af[mt][2], af[mt][3],
                      aAddr[mt] + boff + ks * 32);
#pragma unroll
            for (int p = 0; p < 2; p++) {
                uint32_t r0, r1, r2, r3;
                ldsm4(r0, r1, r2, r3, bAddr[p] + boff + ks * 32);
                bf[p * 2][0] = r0; bf[p * 2][1] = r1;
                bf[p * 2 + 1][0] = r2; bf[p * 2 + 1][1] = r3;
            }
#pragma unroll
            for (int mt = 0; mt < 4; mt++)
#pragma unroll
                for (int nt = 0; nt < 4; nt++)
                    mma8(acc[mt][nt], af[mt], bf[nt]);
        }
        __syncthreads();
        load(c + NSTAGE, c % NSTAGE);
    }

    // ---- epilogue ----
    const int g = lane >> 2, tig = lane & 3;
#pragma unroll
    for (int mt = 0; mt < 4; mt++) {
        const int mrow = m0 + wm * 64 + mt * 16 + g;
        float bR0 = 0.f, bR1 = 0.f;
        if (EPI == 2) { bR0 = bias[mrow]; bR1 = bias[mrow + 8]; }
        if (EPI == 4) { bR0 = 1.0f / rsum[mrow]; bR1 = 1.0f / rsum[mrow + 8]; }
        float rs0 = 0.f, rs1 = 0.f;   // EPI==3 row partial sums
#pragma unroll
        for (int nt = 0; nt < 4; nt++) {
            const int ncol = n0 + wn * 32 + nt * 8 + tig * 2;
            float* cc = acc[mt][nt];
            float2 v0, v1;
            if (EPI == 0) {
                v0.x = cc[0]; v0.y = cc[1]; v1.x = cc[2]; v1.y = cc[3];
            } else if (EPI == 1) {
                float b0 = bias[ncol], b1 = bias[ncol + 1];
                v0.x = rtf(cc[0] + b0); v0.y = rtf(cc[1] + b1);
                v1.x = rtf(cc[2] + b0); v1.y = rtf(cc[3] + b1);
            } else if (EPI == 2) {
                v0.x = rtf(cc[0] + bR0); v0.y = rtf(cc[1] + bR0);
                v1.x = rtf(cc[2] + bR1); v1.y = rtf(cc[3] + bR1);
            } else if (EPI == 3) {
                v0.x = rtf(__expf(cc[0] * alpha));
                v0.y = rtf(__expf(cc[1] * alpha));
                v1.x = rtf(__expf(cc[2] * alpha));
                v1.y = rtf(__expf(cc[3] * alpha));
                rs0 += v0.x + v0.y; rs1 += v1.x + v1.y;
            } else if (EPI == 4) {
                v0.x = rtf(cc[0] * bR0); v0.y = rtf(cc[1] * bR0);
                v1.x = rtf(cc[2] * bR1); v1.y = rtf(cc[3] * bR1);
            } else {  // EPI == 5
                float b0 = bias[ncol], b1 = bias[ncol + 1];
                v0.x = cc[0] + b0; v0.y = cc[1] + b1;
                v1.x = cc[2] + b0; v1.y = cc[3] + b1;
            }
            *reinterpret_cast<float2*>(&C[(size_t)mrow * Nn + ncol]) = v0;
            *reinterpret_cast<float2*>(&C[(size_t)(mrow + 8) * Nn + ncol]) = v1;
        }
        if (EPI == 3) {
            // quad reduction (lanes g*4 .. g*4+3), then one atomic per row
            rs0 += __shfl_xor_sync(~0u, rs0, 1);
            rs0 += __shfl_xor_sync(~0u, rs0, 2);
            rs1 += __shfl_xor_sync(~0u, rs1, 1);
            rs1 += __shfl_xor_sync(~0u, rs1, 2);
            if (tig == 0) {
                atomicAdd(&rsum[mrow], rs0);
                atomicAdd(&rsum[mrow + 8], rs1);
            }
        }
    }
}

// ---------------------------------------------------------------------------
extern "C" void kernel_launch(void* const* d_in, const int* in_sizes, int n_in,
                              void* d_out, int out_size) {
    const float* x  = (const float*)d_in[0];
    const float* Wq = (const float*)d_in[1];
    const float* bq = (const float*)d_in[2];
    const float* Wk = (const float*)d_in[3];
    const float* bk = (const float*)d_in[4];
    const float* Wv = (const float*)d_in[5];
    const float* bv = (const float*)d_in[6];
    const float* Wo = (const float*)d_in[7];
    const float* bo = (const float*)d_in[8];
    float* out = (float*)d_out;

    float *qp, *kp, *vTp, *sp, *op, *xr, *wq, *wk, *wv, *wo, *rs;
    cudaGetSymbolAddress((void**)&qp,  g_q);
    cudaGetSymbolAddress((void**)&kp,  g_k);
    cudaGetSymbolAddress((void**)&vTp, g_vT);
    cudaGetSymbolAddress((void**)&sp,  g_s);
    cudaGetSymbolAddress((void**)&op,  g_o);
    cudaGetSymbolAddress((void**)&xr,  g_xr);
    cudaGetSymbolAddress((void**)&wq,  g_wq);
    cudaGetSymbolAddress((void**)&wk,  g_wk);
    cudaGetSymbolAddress((void**)&wv,  g_wv);
    cudaGetSymbolAddress((void**)&wo,  g_wo);
    cudaGetSymbolAddress((void**)&rs,  g_rsum);

    const float scale = 1.0f / sqrtf((float)HDIM);
    const int SMEM = NSTAGE * BUFB;   // 110592 B

    cudaFuncSetAttribute(gemm_mma<1>, cudaFuncAttributeMaxDynamicSharedMemorySize, SMEM);
    cudaFuncSetAttribute(gemm_mma<2>, cudaFuncAttributeMaxDynamicSharedMemorySize, SMEM);
    cudaFuncSetAttribute(gemm_mma<3>, cudaFuncAttributeMaxDynamicSharedMemorySize, SMEM);
    cudaFuncSetAttribute(gemm_mma<4>, cudaFuncAttributeMaxDynamicSharedMemorySize, SMEM);
    cudaFuncSetAttribute(gemm_mma<5>, cudaFuncAttributeMaxDynamicSharedMemorySize, SMEM);

    dim3 blk(256);

    // ---- pre-round all mainloop operand sources to tf32 ----
    round_tf32<<<(NTOK * CDIM / 4 + 255) / 256, blk>>>(x,  xr, NTOK * CDIM / 4);
    round_tf32<<<(HDIM * CDIM / 4 + 255) / 256, blk>>>(Wq, wq, HDIM * CDIM / 4);
    round_tf32<<<(HDIM * CDIM / 4 + 255) / 256, blk>>>(Wk, wk, HDIM * CDIM / 4);
    round_tf32<<<(CDIM * CDIM / 4 + 255) / 256, blk>>>(Wv, wv, CDIM * CDIM / 4);
    round_tf32<<<(CDIM * CDIM / 4 + 255) / 256, blk>>>(Wo, wo, CDIM * CDIM / 4);
    zero_rsum<<<NTOK / 256, blk>>>(rs);

    // q = x @ Wq.T + bq ; k = x @ Wk.T + bk
    gemm_mma<1><<<dim3(1, 64), blk, SMEM>>>(xr, wq, bq, nullptr, qp, NTOK, HDIM, CDIM, 1.0f);
    gemm_mma<1><<<dim3(1, 64), blk, SMEM>>>(xr, wk, bk, nullptr, kp, NTOK, HDIM, CDIM, 1.0f);

    // vT = Wv @ x.T + bv[m]
    gemm_mma<2><<<dim3(64, 8), blk, SMEM>>>(wv, xr, bv, nullptr, vTp, CDIM, NTOK, CDIM, 1.0f);

    // P_hat = exp(scale * q @ k.T), row sums accumulated into rs
    gemm_mma<3><<<dim3(64, 64), blk, SMEM>>>(qp, kp, nullptr, rs, sp, NTOK, NTOK, HDIM, scale);

    // o = (P_hat @ vT.T) / rowsum
    gemm_mma<4><<<dim3(8, 64), blk, SMEM>>>(sp, vTp, nullptr, rs, op, NTOK, CDIM, NTOK, 1.0f);

    // out = o @ Wo.T + bo
    gemm_mma<5><<<dim3(8, 64), blk, SMEM>>>(op, wo, bo, nullptr, out, NTOK, CDIM, CDIM, 1.0f);
}

// round 8
// speedup vs baseline: 1.5147x; 1.4276x over previous
#include <cuda_runtime.h>
#include <cuda_fp16.h>
#include <math.h>
#include <cstdint>

#define NTOK 8192
#define CDIM 1024
#define HDIM 128

// Scratch (__device__ globals; allocation-free rule)
__device__ float  g_q [(size_t)NTOK * HDIM];
__device__ float  g_k [(size_t)NTOK * HDIM];
__device__ __half g_vTh[(size_t)CDIM * NTOK];  // v transposed, fp16
__device__ __half g_sh [(size_t)NTOK * NTOK];  // 128 MB exp'd scores, fp16 (scaled 1/16)
__device__ float  g_o [(size_t)NTOK * CDIM];
__device__ float  g_xr[(size_t)NTOK * CDIM];   // tf32-rounded x
__device__ float  g_wq[(size_t)HDIM * CDIM];
__device__ float  g_wk[(size_t)HDIM * CDIM];
__device__ float  g_wv[(size_t)CDIM * CDIM];
__device__ float  g_wo[(size_t)CDIM * CDIM];
__device__ float  g_rsum[NTOK];                // softmax row sums (scaled)

// ---------------- portable PTX helpers (sm_80-level only) ----------------
__device__ __forceinline__ uint32_t smem_u32(const void* p) {
    uint32_t a;
    asm("{ .reg .u64 t; cvta.to.shared.u64 t, %1; cvt.u32.u64 %0, t; }"
        : "=r"(a) : "l"(p));
    return a;
}
__device__ __forceinline__ void cp16(uint32_t s, const void* g) {
    asm volatile("cp.async.cg.shared.global [%0], [%1], 16;" :: "r"(s), "l"(g));
}
__device__ __forceinline__ float rtf(float x) {   // round-to-nearest tf32
    uint32_t u;
    asm("cvt.rna.tf32.f32 %0, %1;" : "=r"(u) : "f"(x));
    return __uint_as_float(u);
}
__device__ __forceinline__ void ldsm4(uint32_t& r0, uint32_t& r1,
                                      uint32_t& r2, uint32_t& r3, uint32_t a) {
    asm volatile("ldmatrix.sync.aligned.m8n8.x4.shared.b16 {%0,%1,%2,%3}, [%4];"
                 : "=r"(r0), "=r"(r1), "=r"(r2), "=r"(r3) : "r"(a));
}
__device__ __forceinline__ void mma8(float* c, const uint32_t* a, const uint32_t* b) {
    asm volatile(
        "mma.sync.aligned.m16n8k8.row.col.f32.tf32.tf32.f32 "
        "{%0,%1,%2,%3}, {%4,%5,%6,%7}, {%8,%9}, {%0,%1,%2,%3};"
        : "+f"(c[0]), "+f"(c[1]), "+f"(c[2]), "+f"(c[3])
        : "r"(a[0]), "r"(a[1]), "r"(a[2]), "r"(a[3]), "r"(b[0]), "r"(b[1]));
}
__device__ __forceinline__ void mma16h(float* c, const uint32_t* a, const uint32_t* b) {
    asm volatile(
        "mma.sync.aligned.m16n8k16.row.col.f32.f16.f16.f32 "
        "{%0,%1,%2,%3}, {%4,%5,%6,%7}, {%8,%9}, {%0,%1,%2,%3};"
        : "+f"(c[0]), "+f"(c[1]), "+f"(c[2]), "+f"(c[3])
        : "r"(a[0]), "r"(a[1]), "r"(a[2]), "r"(a[3]), "r"(b[0]), "r"(b[1]));
}

// ---------------------------------------------------------------------------
__global__ __launch_bounds__(256)
void round_tf32(const float* __restrict__ src, float* __restrict__ dst, int n4) {
    int i = blockIdx.x * 256 + threadIdx.x;
    if (i < n4) {
        float4 v = reinterpret_cast<const float4*>(src)[i];
        v.x = rtf(v.x); v.y = rtf(v.y); v.z = rtf(v.z); v.w = rtf(v.w);
        reinterpret_cast<float4*>(dst)[i] = v;
    }
}
__global__ __launch_bounds__(256)
void zero_rsum(float* __restrict__ r) {
    r[blockIdx.x * 256 + threadIdx.x] = 0.f;
}

// ===========================================================================
// tf32 GEMM core (R4 config): CTA 128x128, BK=32, 3-stage cp.async,
// 8 warps 2(M)x4(N), warp tile 64x32, 2 CTAs/SM.
// EPI: 3 = scores: half(exp(acc*alpha)/16) -> half C, rsum atomics
//      5 = acc + bias[n] -> float C (final out-proj)
//      6 = half(acc + bias[m]) -> half C (vT)
// ===========================================================================
#define AST 36
#define TILEB (128 * AST * 4)
#define BUFB  (2 * TILEB)
#define NSTAGE 3

#define GEMM_PROLOG_T                                                          \
    extern __shared__ float sm[];                                              \
    const uint32_t sA = smem_u32(sm);                                          \
    const uint32_t sB = sA + TILEB;                                            \
    const int tid = threadIdx.x;                                               \
    const int lane = tid & 31, wid = tid >> 5;                                 \
    const int wm = wid >> 2, wn = wid & 3;                                     \
    const int q = lane & 7, sub = lane >> 3;                                   \
    uint32_t aAddr[4], bAddr[2];                                               \
    _Pragma("unroll")                                                          \
    for (int mt = 0; mt < 4; mt++)                                             \
        aAddr[mt] = sA + (uint32_t)((wm * 64 + mt * 16 + (sub & 1) * 8 + q) * AST \
                                    + (sub >> 1) * 4) * 4;                     \
    _Pragma("unroll")                                                          \
    for (int p = 0; p < 2; p++)                                                \
        bAddr[p] = sB + (uint32_t)((wn * 32 + p * 16 + (sub >> 1) * 8 + q) * AST \
                                   + (sub & 1) * 4) * 4;

#define GEMM_MAIN_T(Aptr, Bptr, Kdim)                                          \
    const int NC = (Kdim) >> 5;                                                \
    auto load = [&](int c, int b) {                                            \
        if (c < NC) {                                                          \
            const uint32_t aBase = sA + (uint32_t)b * BUFB;                    \
            const uint32_t bBase = sB + (uint32_t)b * BUFB;                    \
            _Pragma("unroll")                                                  \
            for (int it = 0; it < 8; it++) {                                   \
                int i = tid + it * 256;                                        \
                bool isA = i < 1024;                                           \
                int idx = i & 1023;                                            \
                int rr = idx >> 3, cc = idx & 7;                               \
                const float* g = (isA ? (Aptr) : (Bptr)) +                     \
                    (size_t)((isA ? m0 : n0) + rr) * (Kdim) + c * 32 + cc * 4; \
                cp16((isA ? aBase : bBase) + (uint32_t)(rr * AST + cc * 4) * 4, g); \
            }                                                                  \
        }                                                                      \
        asm volatile("cp.async.commit_group;" ::: "memory");                   \
    };                                                                         \
    load(0, 0); load(1, 1); load(2, 2);                                        \
    float acc[4][4][4];                                                        \
    _Pragma("unroll")                                                          \
    for (int i = 0; i < 4; i++)                                                \
        _Pragma("unroll")                                                      \
        for (int j = 0; j < 4; j++)                                            \
            _Pragma("unroll")                                                  \
            for (int r = 0; r < 4; r++) acc[i][j][r] = 0.f;                    \
    for (int c = 0; c < NC; c++) {                                             \
        asm volatile("cp.async.wait_group %0;" :: "n"(NSTAGE - 1) : "memory"); \
        __syncthreads();                                                       \
        const uint32_t boff = (uint32_t)(c % NSTAGE) * BUFB;                   \
        _Pragma("unroll")                                                      \
        for (int ks = 0; ks < 4; ks++) {                                       \
            uint32_t af[4][4], bf[4][2];                                       \
            _Pragma("unroll")                                                  \
            for (int mt = 0; mt < 4; mt++)                                     \
                ldsm4(af[mt][0], af[mt][1], af[mt][2], af[mt][3],              \
                      aAddr[mt] + boff + ks * 32);                             \
            _Pragma("unroll")                                                  \
            for (int p = 0; p < 2; p++) {                                      \
                uint32_t r0, r1, r2, r3;                                       \
                ldsm4(r0, r1, r2, r3, bAddr[p] + boff + ks * 32);              \
                bf[p * 2][0] = r0; bf[p * 2][1] = r1;                          \
                bf[p * 2 + 1][0] = r2; bf[p * 2 + 1][1] = r3;                  \
            }                                                                  \
            _Pragma("unroll")                                                  \
            for (int mt = 0; mt < 4; mt++)                                     \
                _Pragma("unroll")                                              \
                for (int nt = 0; nt < 4; nt++)                                 \
                    mma8(acc[mt][nt], af[mt], bf[nt]);                         \
        }                                                                      \
        __syncthreads();                                                       \
        load(c + NSTAGE, c % NSTAGE);                                          \
    }

template <int EPI>
__global__ __launch_bounds__(256, 2)
void gemm_mma(const float* __restrict__ A, const float* __restrict__ B,
              const float* __restrict__ bias, float* __restrict__ rsum,
              void* __restrict__ Cv, int M, int Nn, int K, float alpha) {
    const int m0 = blockIdx.y * 128, n0 = blockIdx.x * 128;
    GEMM_PROLOG_T
    GEMM_MAIN_T(A, B, K)

    float* Cf = (float*)Cv;
    __half* Ch = (__half*)Cv;
    const int g = lane >> 2, tig = lane & 3;
#pragma unroll
    for (int mt = 0; mt < 4; mt++) {
        const int mrow = m0 + wm * 64 + mt * 16 + g;
        float bR0 = 0.f, bR1 = 0.f;
        if (EPI == 6) { bR0 = bias[mrow]; bR1 = bias[mrow + 8]; }
        float rs0 = 0.f, rs1 = 0.f;
#pragma unroll
        for (int nt = 0; nt < 4; nt++) {
            const int ncol = n0 + wn * 32 + nt * 8 + tig * 2;
            float* cc = acc[mt][nt];
            if (EPI == 3) {
                __half h0 = __float2half_rn(__expf(cc[0] * alpha) * 0.0625f);
                __half h1 = __float2half_rn(__expf(cc[1] * alpha) * 0.0625f);
                __half h2 = __float2half_rn(__expf(cc[2] * alpha) * 0.0625f);
                __half h3 = __float2half_rn(__expf(cc[3] * alpha) * 0.0625f);
                rs0 += __half2float(h0) + __half2float(h1);
                rs1 += __half2float(h2) + __half2float(h3);
                *reinterpret_cast<__half2*>(&Ch[(size_t)mrow * Nn + ncol]) =
                    __halves2half2(h0, h1);
                *reinterpret_cast<__half2*>(&Ch[(size_t)(mrow + 8) * Nn + ncol]) =
                    __halves2half2(h2, h3);
            } else if (EPI == 6) {
                *reinterpret_cast<__half2*>(&Ch[(size_t)mrow * Nn + ncol]) =
                    __halves2half2(__float2half_rn(cc[0] + bR0),
                                   __float2half_rn(cc[1] + bR0));
                *reinterpret_cast<__half2*>(&Ch[(size_t)(mrow + 8) * Nn + ncol]) =
                    __halves2half2(__float2half_rn(cc[2] + bR1),
                                   __float2half_rn(cc[3] + bR1));
            } else {  // EPI == 5
                float b0 = bias[ncol], b1 = bias[ncol + 1];
                float2 v0 = {cc[0] + b0, cc[1] + b1};
                float2 v1 = {cc[2] + b0, cc[3] + b1};
                *reinterpret_cast<float2*>(&Cf[(size_t)mrow * Nn + ncol]) = v0;
                *reinterpret_cast<float2*>(&Cf[(size_t)(mrow + 8) * Nn + ncol]) = v1;
            }
        }
        if (EPI == 3) {
            rs0 += __shfl_xor_sync(~0u, rs0, 1);
            rs0 += __shfl_xor_sync(~0u, rs0, 2);
            rs1 += __shfl_xor_sync(~0u, rs1, 1);
            rs1 += __shfl_xor_sync(~0u, rs1, 2);
            if (tig == 0) {
                atomicAdd(&rsum[mrow], rs0);
                atomicAdd(&rsum[mrow + 8], rs1);
            }
        }
    }
}

// Merged q/k projection: blockIdx.x selects (Wq->q) or (Wk->k). N=128, K=1024.
// C = rtf(acc + bias[n]).
__global__ __launch_bounds__(256, 2)
void gemm_qk(const float* __restrict__ A,
             const float* __restrict__ B0, const float* __restrict__ B1,
             const float* __restrict__ bias0, const float* __restrict__ bias1,
             float* __restrict__ C0, float* __restrict__ C1) {
    const int selk = blockIdx.x;
    const float* Bsel = selk ? B1 : B0;
    const float* bias = selk ? bias1 : bias0;
    float* C = selk ? C1 : C0;
    const int m0 = blockIdx.y * 128, n0 = 0;
    const int Nn = HDIM;
    GEMM_PROLOG_T
    GEMM_MAIN_T(A, Bsel, CDIM)

    const int g = lane >> 2, tig = lane & 3;
#pragma unroll
    for (int mt = 0; mt < 4; mt++) {
        const int mrow = m0 + wm * 64 + mt * 16 + g;
#pragma unroll
        for (int nt = 0; nt < 4; nt++) {
            const int ncol = wn * 32 + nt * 8 + tig * 2;
            float* cc = acc[mt][nt];
            float b0 = bias[ncol], b1 = bias[ncol + 1];
            float2 v0 = {rtf(cc[0] + b0), rtf(cc[1] + b1)};
            float2 v1 = {rtf(cc[2] + b0), rtf(cc[3] + b1)};
            *reinterpret_cast<float2*>(&C[(size_t)mrow * Nn + ncol]) = v0;
            *reinterpret_cast<float2*>(&C[(size_t)(mrow + 8) * Nn + ncol]) = v1;
        }
    }
}

// ===========================================================================
// fp16 GEMM (attn@v): C = (A @ B^T) / rsum[m], A,B fp16 K-major, C float.
// CTA 128x128, BK=32 halves, 3-stage, warp tile 64x32, mma.m16n8k16.
// Padded row stride 40 halves (80 B) -> conflict-free b16 ldmatrix.
// ===========================================================================
#define HST 40                          // halves per padded row
#define HTILEB (128 * HST * 2)          // 10240 B
#define HBUFB  (2 * HTILEB)             // 20480 B per stage

__global__ __launch_bounds__(256, 2)
void gemm_h(const __half* __restrict__ A, const __half* __restrict__ B,
            const float* __restrict__ rsum, float* __restrict__ C,
            int M, int Nn, int K) {
    extern __shared__ float sm[];
    const uint32_t sA = smem_u32(sm);
    const uint32_t sB = sA + HTILEB;

    const int tid = threadIdx.x;
    const int lane = tid & 31, wid = tid >> 5;
    const int wm = wid >> 2, wn = wid & 3;
    const int m0 = blockIdx.y * 128, n0 = blockIdx.x * 128;

    const int q = lane & 7, sub = lane >> 3;
    // A x4: lanes 0-7 rows0-7 k0 | 8-15 rows8-15 k0 | 16-23 rows0-7 k8 | 24-31 rows8-15 k8
    uint32_t aAddr[4];
#pragma unroll
    for (int mt = 0; mt < 4; mt++) {
        int row = wm * 64 + mt * 16 + (sub & 1) * 8 + q;
        int kh  = (sub >> 1) * 8;   // halves
        aAddr[mt] = sA + (uint32_t)(row * HST + kh) * 2;
    }
    // B x4: lanes 0-7 n0-7 k0 | 8-15 n0-7 k8 | 16-23 n8-15 k0 | 24-31 n8-15 k8
    uint32_t bAddr[2];
#pragma unroll
    for (int p = 0; p < 2; p++) {
        int row = wn * 32 + p * 16 + (sub >> 1) * 8 + q;
        int kh  = (sub & 1) * 8;
        bAddr[p] = sB + (uint32_t)(row * HST + kh) * 2;
    }

    const int NC = K >> 5;
    auto load = [&](int c, int b) {
        if (c < NC) {
            const uint32_t aBase = sA + (uint32_t)b * HBUFB;
            const uint32_t bBase = sB + (uint32_t)b * HBUFB;
#pragma unroll
            for (int it = 0; it < 4; it++) {
                int i = tid + it * 256;
                bool isA = i < 512;
                int idx = i & 511;
                int rr = idx >> 2, cc = idx & 3;
                const __half* g = (isA ? A : B) +
                    (size_t)((isA ? m0 : n0) + rr) * K + c * 32 + cc * 8;
                cp16((isA ? aBase : bBase) + (uint32_t)(rr * HST + cc * 8) * 2, g);
            }
        }
        asm volatile("cp.async.commit_group;" ::: "memory");
    };

    load(0, 0); load(1, 1); load(2, 2);

    float acc[4][4][4];
#pragma unroll
    for (int i = 0; i < 4; i++)
#pragma unroll
        for (int j = 0; j < 4; j++)
#pragma unroll
            for (int r = 0; r < 4; r++) acc[i][j][r] = 0.f;

    for (int c = 0; c < NC; c++) {
        asm volatile("cp.async.wait_group %0;" :: "n"(NSTAGE - 1) : "memory");
        __syncthreads();
        const uint32_t boff = (uint32_t)(c % NSTAGE) * HBUFB;
#pragma unroll
        for (int ks = 0; ks < 2; ks++) {        // 2 x k16 per 32-half chunk
            uint32_t af[4][4], bf[4][2];
#pragma unroll
            for (int mt = 0; mt < 4; mt++)
                ldsm4(af[mt][0], af[mt][1], af[mt][2], af[mt][3],
                      aAddr[mt] + boff + ks * 32);
#pragma unroll
            for (int p = 0; p < 2; p++) {
                uint32_t r0, r1, r2, r3;
                ldsm4(r0, r1, r2, r3, bAddr[p] + boff + ks * 32);
                bf[p * 2][0] = r0; bf[p * 2][1] = r1;
                bf[p * 2 + 1][0] = r2; bf[p * 2 + 1][1] = r3;
            }
#pragma unroll
            for (int mt = 0; mt < 4; mt++)
#pragma unroll
                for (int nt = 0; nt < 4; nt++)
                    mma16h(acc[mt][nt], af[mt], bf[nt]);
        }
        __syncthreads();
        load(c + NSTAGE, c % NSTAGE);
    }

    // epilogue: /rsum, tf32-round (feeds out-proj GEMM)
    const int g = lane >> 2, tig = lane & 3;
#pragma unroll
    for (int mt = 0; mt < 4; mt++) {
        const int mrow = m0 + wm * 64 + mt * 16 + g;
        const float r0i = 1.0f / rsum[mrow];
        const float r1i = 1.0f / rsum[mrow + 8];
#pragma unroll
        for (int nt = 0; nt < 4; nt++) {
            const int ncol = n0 + wn * 32 + nt * 8 + tig * 2;
            float* cc = acc[mt][nt];
            float2 v0 = {rtf(cc[0] * r0i), rtf(cc[1] * r0i)};
            float2 v1 = {rtf(cc[2] * r1i), rtf(cc[3] * r1i)};
            *reinterpret_cast<float2*>(&C[(size_t)mrow * Nn + ncol]) = v0;
            *reinterpret_cast<float2*>(&C[(size_t)(mrow + 8) * Nn + ncol]) = v1;
        }
    }
}

// ---------------------------------------------------------------------------
extern "C" void kernel_launch(void* const* d_in, const int* in_sizes, int n_in,
                              void* d_out, int out_size) {
    const float* x  = (const float*)d_in[0];
    const float* Wq = (const float*)d_in[1];
    const float* bq = (const float*)d_in[2];
    const float* Wk = (const float*)d_in[3];
    const float* bk = (const float*)d_in[4];
    const float* Wv = (const float*)d_in[5];
    const float* bv = (const float*)d_in[6];
    const float* Wo = (const float*)d_in[7];
    const float* bo = (const float*)d_in[8];
    float* out = (float*)d_out;

    float *qp, *kp, *op, *xr, *wq, *wk, *wv, *wo, *rs;
    __half *vTh, *sh;
    cudaGetSymbolAddress((void**)&qp,  g_q);
    cudaGetSymbolAddress((void**)&kp,  g_k);
    cudaGetSymbolAddress((void**)&vTh, g_vTh);
    cudaGetSymbolAddress((void**)&sh,  g_sh);
    cudaGetSymbolAddress((void**)&op,  g_o);
    cudaGetSymbolAddress((void**)&xr,  g_xr);
    cudaGetSymbolAddress((void**)&wq,  g_wq);
    cudaGetSymbolAddress((void**)&wk,  g_wk);
    cudaGetSymbolAddress((void**)&wv,  g_wv);
    cudaGetSymbolAddress((void**)&wo,  g_wo);
    cudaGetSymbolAddress((void**)&rs,  g_rsum);

    const float scale = 1.0f / sqrtf((float)HDIM);
    const int SMEM  = NSTAGE * BUFB;    // 110592
    const int SMEMH = NSTAGE * HBUFB;   // 61440

    cudaFuncSetAttribute(gemm_qk,     cudaFuncAttributeMaxDynamicSharedMemorySize, SMEM);
    cudaFuncSetAttribute(gemm_mma<3>, cudaFuncAttributeMaxDynamicSharedMemorySize, SMEM);
    cudaFuncSetAttribute(gemm_mma<5>, cudaFuncAttributeMaxDynamicSharedMemorySize, SMEM);
    cudaFuncSetAttribute(gemm_mma<6>, cudaFuncAttributeMaxDynamicSharedMemorySize, SMEM);
    cudaFuncSetAttribute(gemm_h,      cudaFuncAttributeMaxDynamicSharedMemorySize, SMEMH);

    dim3 blk(256);

    // ---- pre-round mainloop operand sources to tf32 ----
    round_tf32<<<(NTOK * CDIM / 4 + 255) / 256, blk>>>(x,  xr, NTOK * CDIM / 4);
    round_tf32<<<(HDIM * CDIM / 4 + 255) / 256, blk>>>(Wq, wq, HDIM * CDIM / 4);
    round_tf32<<<(HDIM * CDIM / 4 + 255) / 256, blk>>>(Wk, wk, HDIM * CDIM / 4);
    round_tf32<<<(CDIM * CDIM / 4 + 255) / 256, blk>>>(Wv, wv, CDIM * CDIM / 4);
    round_tf32<<<(CDIM * CDIM / 4 + 255) / 256, blk>>>(Wo, wo, CDIM * CDIM / 4);
    zero_rsum<<<NTOK / 256, blk>>>(rs);

    // q,k projections merged: grid (2, 64)
    gemm_qk<<<dim3(2, 64), blk, SMEM>>>(xr, wq, wk, bq, bk, qp, kp);

    // vT = Wv @ x.T + bv[m] -> fp16
    gemm_mma<6><<<dim3(64, 8), blk, SMEM>>>(wv, xr, bv, nullptr, vTh, CDIM, NTOK, CDIM, 1.0f);

    // P_hat = fp16(exp(scale * q@k.T)/16) + rsum atomics
    gemm_mma<3><<<dim3(64, 64), blk, SMEM>>>(qp, kp, nullptr, rs, sh, NTOK, NTOK, HDIM, scale);

    // o = (P_hat @ vT.T) / rsum   (fp16 MMA, fp32 accum)
    gemm_h<<<dim3(8, 64), blk, SMEMH>>>(sh, vTh, rs, op, NTOK, CDIM, NTOK);

    // out = o @ Wo.T + bo
    gemm_mma<5><<<dim3(8, 64), blk, SMEM>>>(op, wo, bo, nullptr, out, NTOK, CDIM, CDIM, 1.0f);
}

// round 9
// speedup vs baseline: 1.7627x; 1.1638x over previous
#include <cuda_runtime.h>
#include <cuda_fp16.h>
#include <math.h>
#include <cstdint>

#define NTOK 8192
#define CDIM 1024
#define HDIM 128

// Scratch (__device__ globals; allocation-free rule)
__device__ __half g_xh [(size_t)NTOK * CDIM];   // fp16 x
__device__ __half g_wqh[(size_t)HDIM * CDIM];
__device__ __half g_wkh[(size_t)HDIM * CDIM];
__device__ __half g_wvh[(size_t)CDIM * CDIM];
__device__ __half g_woh[(size_t)CDIM * CDIM];
__device__ __half g_qh [(size_t)NTOK * HDIM];
__device__ __half g_kh [(size_t)NTOK * HDIM];
__device__ __half g_vTh[(size_t)CDIM * NTOK];   // v transposed, fp16
__device__ __half g_sh [(size_t)NTOK * NTOK];   // exp'd scores fp16 (scaled 1/16)
__device__ __half g_oh [(size_t)NTOK * CDIM];   // attn output, fp16
__device__ float  g_rsum[NTOK];                 // softmax row sums (scaled)

// ---------------- portable PTX helpers (sm_80-level only) ----------------
__device__ __forceinline__ uint32_t smem_u32(const void* p) {
    uint32_t a;
    asm("{ .reg .u64 t; cvta.to.shared.u64 t, %1; cvt.u32.u64 %0, t; }"
        : "=r"(a) : "l"(p));
    return a;
}
__device__ __forceinline__ void cp16(uint32_t s, const void* g) {
    asm volatile("cp.async.cg.shared.global [%0], [%1], 16;" :: "r"(s), "l"(g));
}
__device__ __forceinline__ void ldsm4(uint32_t& r0, uint32_t& r1,
                                      uint32_t& r2, uint32_t& r3, uint32_t a) {
    asm volatile("ldmatrix.sync.aligned.m8n8.x4.shared.b16 {%0,%1,%2,%3}, [%4];"
                 : "=r"(r0), "=r"(r1), "=r"(r2), "=r"(r3) : "r"(a));
}
__device__ __forceinline__ void mma16h(float* c, const uint32_t* a, const uint32_t* b) {
    asm volatile(
        "mma.sync.aligned.m16n8k16.row.col.f32.f16.f16.f32 "
        "{%0,%1,%2,%3}, {%4,%5,%6,%7}, {%8,%9}, {%0,%1,%2,%3};"
        : "+f"(c[0]), "+f"(c[1]), "+f"(c[2]), "+f"(c[3])
        : "r"(a[0]), "r"(a[1]), "r"(a[2]), "r"(a[3]), "r"(b[0]), "r"(b[1]));
}

// ---------------------------------------------------------------------------
__global__ __launch_bounds__(256)
void f2h(const float* __restrict__ src, __half* __restrict__ dst, int n4) {
    int i = blockIdx.x * 256 + threadIdx.x;
    if (i < n4) {
        float4 v = reinterpret_cast<const float4*>(src)[i];
        __half2 h0 = __halves2half2(__float2half_rn(v.x), __float2half_rn(v.y));
        __half2 h1 = __halves2half2(__float2half_rn(v.z), __float2half_rn(v.w));
        reinterpret_cast<__half2*>(dst)[i * 2]     = h0;
        reinterpret_cast<__half2*>(dst)[i * 2 + 1] = h1;
    }
}
__global__ __launch_bounds__(256)
void zero_rsum(float* __restrict__ r) {
    r[blockIdx.x * 256 + threadIdx.x] = 0.f;
}

// ===========================================================================
// fp16 tensor-core GEMM: C = A @ B^T (+epilogue), A:(M,K) B:(Nn,K) fp16 K-major.
// CTA 128x128, BK=32 halves, 3-stage cp.async, 8 warps 2(M)x4(N),
// warp tile 64x32, mma.m16n8k16, fp32 accum, 2 CTAs/SM.
// Padded rows: 40 halves (80 B) -> conflict-free b16 ldmatrix.
// EPI: 3 = half(exp(acc*alpha)/16) -> half C, rsum atomics  (scores)
//      4 = half(acc / rsum[m])     -> half C                (attn@v)
//      5 = acc + bias[n]           -> float C               (final out-proj)
//      6 = half(acc + bias[m])     -> half C                (vT)
// ===========================================================================
#define HST 40
#define HTILEB (128 * HST * 2)          // 10240 B
#define HBUFB  (2 * HTILEB)             // 20480 B per stage
#define NSTAGE 3

#define GEMMH_PROLOG                                                            \
    extern __shared__ float sm[];                                               \
    const uint32_t sA = smem_u32(sm);                                           \
    const uint32_t sB = sA + HTILEB;                                            \
    const int tid = threadIdx.x;                                                \
    const int lane = tid & 31, wid = tid >> 5;                                  \
    const int wm = wid >> 2, wn = wid & 3;                                      \
    const int q = lane & 7, sub = lane >> 3;                                    \
    uint32_t aAddr[4], bAddr[2];                                                \
    _Pragma("unroll")                                                           \
    for (int mt = 0; mt < 4; mt++) {                                            \
        int row = wm * 64 + mt * 16 + (sub & 1) * 8 + q;                        \
        aAddr[mt] = sA + (uint32_t)(row * HST + (sub >> 1) * 8) * 2;            \
    }                                                                           \
    _Pragma("unroll")                                                           \
    for (int p = 0; p < 2; p++) {                                               \
        int row = wn * 32 + p * 16 + (sub >> 1) * 8 + q;                        \
        bAddr[p] = sB + (uint32_t)(row * HST + (sub & 1) * 8) * 2;              \
    }

#define GEMMH_MAIN(Aptr, Bptr, Kdim)                                            \
    const int NC = (Kdim) >> 5;                                                 \
    auto load = [&](int c, int b) {                                             \
        if (c < NC) {                                                           \
            const uint32_t aBase = sA + (uint32_t)b * HBUFB;                    \
            const uint32_t bBase = sB + (uint32_t)b * HBUFB;                    \
            _Pragma("unroll")                                                   \
            for (int it = 0; it < 4; it++) {                                    \
                int i = tid + it * 256;                                         \
                bool isA = i < 512;                                             \
                int idx = i & 511;                                              \
                int rr = idx >> 2, cc = idx & 3;                                \
                const __half* g = (isA ? (Aptr) : (Bptr)) +                     \
                    (size_t)((isA ? m0 : n0) + rr) * (Kdim) + c * 32 + cc * 8;  \
                cp16((isA ? aBase : bBase) + (uint32_t)(rr * HST + cc * 8) * 2, g); \
            }                                                                   \
        }                                                                       \
        asm volatile("cp.async.commit_group;" ::: "memory");                    \
    };                                                                          \
    load(0, 0); load(1, 1); load(2, 2);                                         \
    float acc[4][4][4];                                                         \
    _Pragma("unroll")                                                           \
    for (int i = 0; i < 4; i++)                                                 \
        _Pragma("unroll")                                                       \
        for (int j = 0; j < 4; j++)                                             \
            _Pragma("unroll")                                                   \
            for (int r = 0; r < 4; r++) acc[i][j][r] = 0.f;                     \
    for (int c = 0; c < NC; c++) {                                              \
        asm volatile("cp.async.wait_group %0;" :: "n"(NSTAGE - 1) : "memory");  \
        __syncthreads();                                                        \
        const uint32_t boff = (uint32_t)(c % NSTAGE) * HBUFB;                   \
        _Pragma("unroll")                                                       \
        for (int ks = 0; ks < 2; ks++) {                                        \
            uint32_t af[4][4], bf[4][2];                                        \
            _Pragma("unroll")                                                   \
            for (int mt = 0; mt < 4; mt++)                                      \
                ldsm4(af[mt][0], af[mt][1], af[mt][2], af[mt][3],               \
                      aAddr[mt] + boff + ks * 32);                              \
            _Pragma("unroll")                                                   \
            for (int p = 0; p < 2; p++) {                                       \
                uint32_t r0, r1, r2, r3;                                        \
                ldsm4(r0, r1, r2, r3, bAddr[p] + boff + ks * 32);               \
                bf[p * 2][0] = r0; bf[p * 2][1] = r1;                           \
                bf[p * 2 + 1][0] = r2; bf[p * 2 + 1][1] = r3;                   \
            }                                                                   \
            _Pragma("unroll")                                                   \
            for (int mt = 0; mt < 4; mt++)                                      \
                _Pragma("unroll")                                               \
                for (int nt = 0; nt < 4; nt++)                                  \
                    mma16h(acc[mt][nt], af[mt], bf[nt]);                        \
        }                                                                       \
        __syncthreads();                                                        \
        load(c + NSTAGE, c % NSTAGE);                                           \
    }

template <int EPI>
__global__ __launch_bounds__(256, 2)
void gemm_h(const __half* __restrict__ A, const __half* __restrict__ B,
            const float* __restrict__ bias, float* __restrict__ rsum,
            void* __restrict__ Cv, int M, int Nn, int K, float alpha) {
    const int m0 = blockIdx.y * 128, n0 = blockIdx.x * 128;
    GEMMH_PROLOG
    GEMMH_MAIN(A, B, K)

    float* Cf = (float*)Cv;
    __half* Ch = (__half*)Cv;
    const int g = lane >> 2, tig = lane & 3;
#pragma unroll
    for (int mt = 0; mt < 4; mt++) {
        const int mrow = m0 + wm * 64 + mt * 16 + g;
        float bR0 = 0.f, bR1 = 0.f;
        if (EPI == 6) { bR0 = bias[mrow]; bR1 = bias[mrow + 8]; }
        if (EPI == 4) { bR0 = 1.0f / rsum[mrow]; bR1 = 1.0f / rsum[mrow + 8]; }
        float rs0 = 0.f, rs1 = 0.f;
#pragma unroll
        for (int nt = 0; nt < 4; nt++) {
            const int ncol = n0 + wn * 32 + nt * 8 + tig * 2;
            float* cc = acc[mt][nt];
            if (EPI == 3) {
                __half h0 = __float2half_rn(__expf(cc[0] * alpha) * 0.0625f);
                __half h1 = __float2half_rn(__expf(cc[1] * alpha) * 0.0625f);
                __half h2 = __float2half_rn(__expf(cc[2] * alpha) * 0.0625f);
                __half h3 = __float2half_rn(__expf(cc[3] * alpha) * 0.0625f);
                rs0 += __half2float(h0) + __half2float(h1);
                rs1 += __half2float(h2) + __half2float(h3);
                *reinterpret_cast<__half2*>(&Ch[(size_t)mrow * Nn + ncol]) =
                    __halves2half2(h0, h1);
                *reinterpret_cast<__half2*>(&Ch[(size_t)(mrow + 8) * Nn + ncol]) =
                    __halves2half2(h2, h3);
            } else if (EPI == 4) {
                *reinterpret_cast<__half2*>(&Ch[(size_t)mrow * Nn + ncol]) =
                    __halves2half2(__float2half_rn(cc[0] * bR0),
                                   __float2half_rn(cc[1] * bR0));
                *reinterpret_cast<__half2*>(&Ch[(size_t)(mrow + 8) * Nn + ncol]) =
                    __halves2half2(__float2half_rn(cc[2] * bR1),
                                   __float2half_rn(cc[3] * bR1));
            } else if (EPI == 6) {
                *reinterpret_cast<__half2*>(&Ch[(size_t)mrow * Nn + ncol]) =
                    __halves2half2(__float2half_rn(cc[0] + bR0),
                                   __float2half_rn(cc[1] + bR0));
                *reinterpret_cast<__half2*>(&Ch[(size_t)(mrow + 8) * Nn + ncol]) =
                    __halves2half2(__float2half_rn(cc[2] + bR1),
                                   __float2half_rn(cc[3] + bR1));
            } else {  // EPI == 5: final, float out + bias[n]
                float b0 = bias[ncol], b1 = bias[ncol + 1];
                float2 v0 = {cc[0] + b0, cc[1] + b1};
                float2 v1 = {cc[2] + b0, cc[3] + b1};
                *reinterpret_cast<float2*>(&Cf[(size_t)mrow * Nn + ncol]) = v0;
                *reinterpret_cast<float2*>(&Cf[(size_t)(mrow + 8) * Nn + ncol]) = v1;
            }
        }
        if (EPI == 3) {
            rs0 += __shfl_xor_sync(~0u, rs0, 1);
            rs0 += __shfl_xor_sync(~0u, rs0, 2);
            rs1 += __shfl_xor_sync(~0u, rs1, 1);
            rs1 += __shfl_xor_sync(~0u, rs1, 2);
            if (tig == 0) {
                atomicAdd(&rsum[mrow], rs0);
                atomicAdd(&rsum[mrow + 8], rs1);
            }
        }
    }
}

// Merged q/k projection (fp16): blockIdx.x selects Wq->q or Wk->k.
// N=128, K=1024. C = half(acc + bias[n]).
__global__ __launch_bounds__(256, 2)
void gemm_qk(const __half* __restrict__ A,
             const __half* __restrict__ B0, const __half* __restrict__ B1,
             const float* __restrict__ bias0, const float* __restrict__ bias1,
             __half* __restrict__ C0, __half* __restrict__ C1) {
    const int selk = blockIdx.x;
    const __half* Bsel = selk ? B1 : B0;
    const float* bias = selk ? bias1 : bias0;
    __half* C = selk ? C1 : C0;
    const int m0 = blockIdx.y * 128, n0 = 0;
    const int Nn = HDIM;
    GEMMH_PROLOG
    GEMMH_MAIN(A, Bsel, CDIM)

    const int g = lane >> 2, tig = lane & 3;
#pragma unroll
    for (int mt = 0; mt < 4; mt++) {
        const int mrow = m0 + wm * 64 + mt * 16 + g;
#pragma unroll
        for (int nt = 0; nt < 4; nt++) {
            const int ncol = wn * 32 + nt * 8 + tig * 2;
            float* cc = acc[mt][nt];
            float b0 = bias[ncol], b1 = bias[ncol + 1];
            *reinterpret_cast<__half2*>(&C[(size_t)mrow * Nn + ncol]) =
                __halves2half2(__float2half_rn(cc[0] + b0),
                               __float2half_rn(cc[1] + b1));
            *reinterpret_cast<__half2*>(&C[(size_t)(mrow + 8) * Nn + ncol]) =
                __halves2half2(__float2half_rn(cc[2] + b0),
                               __float2half_rn(cc[3] + b1));
        }
    }
}

// ---------------------------------------------------------------------------
extern "C" void kernel_launch(void* const* d_in, const int* in_sizes, int n_in,
                              void* d_out, int out_size) {
    const float* x  = (const float*)d_in[0];
    const float* Wq = (const float*)d_in[1];
    const float* bq = (const float*)d_in[2];
    const float* Wk = (const float*)d_in[3];
    const float* bk = (const float*)d_in[4];
    const float* Wv = (const float*)d_in[5];
    const float* bv = (const float*)d_in[6];
    const float* Wo = (const float*)d_in[7];
    const float* bo = (const float*)d_in[8];
    float* out = (float*)d_out;

    __half *xh, *wqh, *wkh, *wvh, *woh, *qh, *kh, *vTh, *sh, *oh;
    float *rs;
    cudaGetSymbolAddress((void**)&xh,  g_xh);
    cudaGetSymbolAddress((void**)&wqh, g_wqh);
    cudaGetSymbolAddress((void**)&wkh, g_wkh);
    cudaGetSymbolAddress((void**)&wvh, g_wvh);
    cudaGetSymbolAddress((void**)&woh, g_woh);
    cudaGetSymbolAddress((void**)&qh,  g_qh);
    cudaGetSymbolAddress((void**)&kh,  g_kh);
    cudaGetSymbolAddress((void**)&vTh, g_vTh);
    cudaGetSymbolAddress((void**)&sh,  g_sh);
    cudaGetSymbolAddress((void**)&oh,  g_oh);
    cudaGetSymbolAddress((void**)&rs,  g_rsum);

    const float scale = 1.0f / sqrtf((float)HDIM);
    const int SMEMH = NSTAGE * HBUFB;   // 61440

    cudaFuncSetAttribute(gemm_qk,    cudaFuncAttributeMaxDynamicSharedMemorySize, SMEMH);
    cudaFuncSetAttribute(gemm_h<3>,  cudaFuncAttributeMaxDynamicSharedMemorySize, SMEMH);
    cudaFuncSetAttribute(gemm_h<4>,  cudaFuncAttributeMaxDynamicSharedMemorySize, SMEMH);
    cudaFuncSetAttribute(gemm_h<5>,  cudaFuncAttributeMaxDynamicSharedMemorySize, SMEMH);
    cudaFuncSetAttribute(gemm_h<6>,  cudaFuncAttributeMaxDynamicSharedMemorySize, SMEMH);

    dim3 blk(256);

    // ---- convert operands to fp16 ----
    f2h<<<(NTOK * CDIM / 4 + 255) / 256, blk>>>(x,  xh,  NTOK * CDIM / 4);
    f2h<<<(HDIM * CDIM / 4 + 255) / 256, blk>>>(Wq, wqh, HDIM * CDIM / 4);
    f2h<<<(HDIM * CDIM / 4 + 255) / 256, blk>>>(Wk, wkh, HDIM * CDIM / 4);
    f2h<<<(CDIM * CDIM / 4 + 255) / 256, blk>>>(Wv, wvh, CDIM * CDIM / 4);
    f2h<<<(CDIM * CDIM / 4 + 255) / 256, blk>>>(Wo, woh, CDIM * CDIM / 4);
    zero_rsum<<<NTOK / 256, blk>>>(rs);

    // q,k projections merged: grid (2, 64)
    gemm_qk<<<dim3(2, 64), blk, SMEMH>>>(xh, wqh, wkh, bq, bk, qh, kh);

    // vT = Wv @ x.T + bv[m] -> fp16
    gemm_h<6><<<dim3(64, 8), blk, SMEMH>>>(wvh, xh, bv, nullptr, vTh, CDIM, NTOK, CDIM, 1.0f);

    // P_hat = fp16(exp(scale * q@k.T)/16) + rsum atomics
    gemm_h<3><<<dim3(64, 64), blk, SMEMH>>>(qh, kh, nullptr, rs, sh, NTOK, NTOK, HDIM, scale);

    // o = fp16((P_hat @ vT.T) / rsum)
    gemm_h<4><<<dim3(8, 64), blk, SMEMH>>>(sh, vTh, nullptr, rs, oh, NTOK, CDIM, NTOK, 1.0f);

    // out = o @ Wo.T + bo  (float out)
    gemm_h<5><<<dim3(8, 64), blk, SMEMH>>>(oh, woh, bo, nullptr, out, NTOK, CDIM, CDIM, 1.0f);
}

// round 10
// speedup vs baseline: 1.9056x; 1.0810x over previous
#include <cuda_runtime.h>
#include <cuda_fp16.h>
#include <math.h>
#include <cstdint>

#define NTOK 8192
#define CDIM 1024
#define HDIM 128

// Scratch (__device__ globals; allocation-free rule)
__device__ __half g_xh [(size_t)NTOK * CDIM];   // fp16 x
__device__ __half g_wqh[(size_t)HDIM * CDIM];
__device__ __half g_wkh[(size_t)HDIM * CDIM];
__device__ __half g_wvh[(size_t)CDIM * CDIM];
__device__ __half g_woh[(size_t)CDIM * CDIM];
__device__ __half g_qh [(size_t)NTOK * HDIM];
__device__ __half g_kh [(size_t)NTOK * HDIM];
__device__ __half g_vTh[(size_t)CDIM * NTOK];   // v transposed, fp16
__device__ __half g_sh [(size_t)NTOK * NTOK];   // exp'd scores fp16 (scaled 1/16)
__device__ __half g_oh [(size_t)NTOK * CDIM];   // attn output, fp16
__device__ float  g_rsum[NTOK];                 // softmax row sums (scaled)

// ---------------- portable PTX helpers (sm_80-level only) ----------------
__device__ __forceinline__ uint32_t smem_u32(const void* p) {
    uint32_t a;
    asm("{ .reg .u64 t; cvta.to.shared.u64 t, %1; cvt.u32.u64 %0, t; }"
        : "=r"(a) : "l"(p));
    return a;
}
__device__ __forceinline__ void cp16(uint32_t s, const void* g) {
    asm volatile("cp.async.cg.shared.global [%0], [%1], 16;" :: "r"(s), "l"(g));
}
__device__ __forceinline__ void ldsm4(uint32_t& r0, uint32_t& r1,
                                      uint32_t& r2, uint32_t& r3, uint32_t a) {
    asm volatile("ldmatrix.sync.aligned.m8n8.x4.shared.b16 {%0,%1,%2,%3}, [%4];"
                 : "=r"(r0), "=r"(r1), "=r"(r2), "=r"(r3) : "r"(a));
}
__device__ __forceinline__ void mma16h(float* c, const uint32_t* a, const uint32_t* b) {
    asm volatile(
        "mma.sync.aligned.m16n8k16.row.col.f32.f16.f16.f32 "
        "{%0,%1,%2,%3}, {%4,%5,%6,%7}, {%8,%9}, {%0,%1,%2,%3};"
        : "+f"(c[0]), "+f"(c[1]), "+f"(c[2]), "+f"(c[3])
        : "r"(a[0]), "r"(a[1]), "r"(a[2]), "r"(a[3]), "r"(b[0]), "r"(b[1]));
}

// ---------------------------------------------------------------------------
__global__ __launch_bounds__(256)
void f2h(const float* __restrict__ src, __half* __restrict__ dst, int n4) {
    int i = blockIdx.x * 256 + threadIdx.x;
    if (i < n4) {
        float4 v = reinterpret_cast<const float4*>(src)[i];
        __half2 h0 = __halves2half2(__float2half_rn(v.x), __float2half_rn(v.y));
        __half2 h1 = __halves2half2(__float2half_rn(v.z), __float2half_rn(v.w));
        reinterpret_cast<__half2*>(dst)[i * 2]     = h0;
        reinterpret_cast<__half2*>(dst)[i * 2 + 1] = h1;
    }
}
__global__ __launch_bounds__(256)
void zero_rsum(float* __restrict__ r) {
    r[blockIdx.x * 256 + threadIdx.x] = 0.f;
}

// ===========================================================================
// fp16 tensor-core GEMM: C = A @ B^T (+epilogue), A:(M,K) B:(Nn,K) fp16 K-major.
// CTA 128x128, BK=32 halves, 4-stage cp.async, 8 warps 2(M)x4(N),
// warp tile 64x32, mma.m16n8k16, fp32 accum, 2 CTAs/SM.
// Padded rows: 40 halves (80 B) -> conflict-free b16 ldmatrix.
// EPI: 3 = half(exp(acc*alpha)/16) -> half C, rsum atomics  (scores)
//      4 = half(acc / rsum[m])     -> half C                (attn@v)
//      5 = acc + bias[n]           -> float C               (final out-proj)
//      6 = half(acc + bias[m])     -> half C                (vT)
// ===========================================================================
#define HST 40
#define HTILEB (128 * HST * 2)          // 10240 B
#define HBUFB  (2 * HTILEB)             // 20480 B per stage
#define NSTAGE 4

#define GEMMH_PROLOG                                                            \
    extern __shared__ float sm[];                                               \
    const uint32_t sA = smem_u32(sm);                                           \
    const uint32_t sB = sA + HTILEB;                                            \
    const int tid = threadIdx.x;                                                \
    const int lane = tid & 31, wid = tid >> 5;                                  \
    const int wm = wid >> 2, wn = wid & 3;                                      \
    const int q = lane & 7, sub = lane >> 3;                                    \
    uint32_t aAddr[4], bAddr[2];                                                \
    _Pragma("unroll")                                                           \
    for (int mt = 0; mt < 4; mt++) {                                            \
        int row = wm * 64 + mt * 16 + (sub & 1) * 8 + q;                        \
        aAddr[mt] = sA + (uint32_t)(row * HST + (sub >> 1) * 8) * 2;            \
    }                                                                           \
    _Pragma("unroll")                                                           \
    for (int p = 0; p < 2; p++) {                                               \
        int row = wn * 32 + p * 16 + (sub >> 1) * 8 + q;                        \
        bAddr[p] = sB + (uint32_t)(row * HST + (sub & 1) * 8) * 2;              \
    }

#define GEMMH_MAIN(Aptr, Bptr, Kdim)                                            \
    const int NC = (Kdim) >> 5;                                                 \
    auto load = [&](int c, int b) {                                             \
        if (c < NC) {                                                           \
            const uint32_t aBase = sA + (uint32_t)b * HBUFB;                    \
            const uint32_t bBase = sB + (uint32_t)b * HBUFB;                    \
            _Pragma("unroll")                                                   \
            for (int it = 0; it < 4; it++) {                                    \
                int i = tid + it * 256;                                         \
                bool isA = i < 512;                                             \
                int idx = i & 511;                                              \
                int rr = idx >> 2, cc = idx & 3;                                \
                const __half* g = (isA ? (Aptr) : (Bptr)) +                     \
                    (size_t)((isA ? m0 : n0) + rr) * (Kdim) + c * 32 + cc * 8;  \
                cp16((isA ? aBase : bBase) + (uint32_t)(rr * HST + cc * 8) * 2, g); \
            }                                                                   \
        }                                                                       \
        asm volatile("cp.async.commit_group;" ::: "memory");                    \
    };                                                                          \
    _Pragma("unroll")                                                           \
    for (int s = 0; s < NSTAGE; s++) load(s, s);                                \
    float acc[4][4][4];                                                         \
    _Pragma("unroll")                                                           \
    for (int i = 0; i < 4; i++)                                                 \
        _Pragma("unroll")                                                       \
        for (int j = 0; j < 4; j++)                                             \
            _Pragma("unroll")                                                   \
            for (int r = 0; r < 4; r++) acc[i][j][r] = 0.f;                     \
    for (int c = 0; c < NC; c++) {                                              \
        asm volatile("cp.async.wait_group %0;" :: "n"(NSTAGE - 1) : "memory");  \
        __syncthreads();                                                        \
        const uint32_t boff = (uint32_t)(c % NSTAGE) * HBUFB;                   \
        _Pragma("unroll")                                                       \
        for (int ks = 0; ks < 2; ks++) {                                        \
            uint32_t af[4][4], bf[4][2];                                        \
            _Pragma("unroll")                                                   \
            for (int mt = 0; mt < 4; mt++)                                      \
                ldsm4(af[mt][0], af[mt][1], af[mt][2], af[mt][3],               \
                      aAddr[mt] + boff + ks * 32);                              \
            _Pragma("unroll")                                                   \
            for (int p = 0; p < 2; p++) {                                       \
                uint32_t r0, r1, r2, r3;                                        \
                ldsm4(r0, r1, r2, r3, bAddr[p] + boff + ks * 32);               \
                bf[p * 2][0] = r0; bf[p * 2][1] = r1;                           \
                bf[p * 2 + 1][0] = r2; bf[p * 2 + 1][1] = r3;                   \
            }                                                                   \
            _Pragma("unroll")                                                   \
            for (int mt = 0; mt < 4; mt++)                                      \
                _Pragma("unroll")                                               \
                for (int nt = 0; nt < 4; nt++)                                  \
                    mma16h(acc[mt][nt], af[mt], bf[nt]);                        \
        }                                                                       \
        __syncthreads();                                                        \
        load(c + NSTAGE, c % NSTAGE);                                           \
    }

template <int EPI>
__global__ __launch_bounds__(256, 2)
void gemm_h(const __half* __restrict__ A, const __half* __restrict__ B,
            const float* __restrict__ bias, float* __restrict__ rsum,
            void* __restrict__ Cv, int M, int Nn, int K, float alpha) {
    const int m0 = blockIdx.y * 128, n0 = blockIdx.x * 128;
    GEMMH_PROLOG
    GEMMH_MAIN(A, B, K)

    float* Cf = (float*)Cv;
    __half* Ch = (__half*)Cv;
    const int g = lane >> 2, tig = lane & 3;
#pragma unroll
    for (int mt = 0; mt < 4; mt++) {
        const int mrow = m0 + wm * 64 + mt * 16 + g;
        float bR0 = 0.f, bR1 = 0.f;
        if (EPI == 6) { bR0 = bias[mrow]; bR1 = bias[mrow + 8]; }
        if (EPI == 4) { bR0 = 1.0f / rsum[mrow]; bR1 = 1.0f / rsum[mrow + 8]; }
        float rs0 = 0.f, rs1 = 0.f;
#pragma unroll
        for (int nt = 0; nt < 4; nt++) {
            const int ncol = n0 + wn * 32 + nt * 8 + tig * 2;
            float* cc = acc[mt][nt];
            if (EPI == 3) {
                __half h0 = __float2half_rn(__expf(cc[0] * alpha) * 0.0625f);
                __half h1 = __float2half_rn(__expf(cc[1] * alpha) * 0.0625f);
                __half h2 = __float2half_rn(__expf(cc[2] * alpha) * 0.0625f);
                __half h3 = __float2half_rn(__expf(cc[3] * alpha) * 0.0625f);
                rs0 += __half2float(h0) + __half2float(h1);
                rs1 += __half2float(h2) + __half2float(h3);
                *reinterpret_cast<__half2*>(&Ch[(size_t)mrow * Nn + ncol]) =
                    __halves2half2(h0, h1);
                *reinterpret_cast<__half2*>(&Ch[(size_t)(mrow + 8) * Nn + ncol]) =
                    __halves2half2(h2, h3);
            } else if (EPI == 4) {
                *reinterpret_cast<__half2*>(&Ch[(size_t)mrow * Nn + ncol]) =
                    __halves2half2(__float2half_rn(cc[0] * bR0),
                                   __float2half_rn(cc[1] * bR0));
                *reinterpret_cast<__half2*>(&Ch[(size_t)(mrow + 8) * Nn + ncol]) =
                    __halves2half2(__float2half_rn(cc[2] * bR1),
                                   __float2half_rn(cc[3] * bR1));
            } else if (EPI == 6) {
                *reinterpret_cast<__half2*>(&Ch[(size_t)mrow * Nn + ncol]) =
                    __halves2half2(__float2half_rn(cc[0] + bR0),
                                   __float2half_rn(cc[1] + bR0));
                *reinterpret_cast<__half2*>(&Ch[(size_t)(mrow + 8) * Nn + ncol]) =
                    __halves2half2(__float2half_rn(cc[2] + bR1),
                                   __float2half_rn(cc[3] + bR1));
            } else {  // EPI == 5: final, float out + bias[n]
                float b0 = bias[ncol], b1 = bias[ncol + 1];
                float2 v0 = {cc[0] + b0, cc[1] + b1};
                float2 v1 = {cc[2] + b0, cc[3] + b1};
                *reinterpret_cast<float2*>(&Cf[(size_t)mrow * Nn + ncol]) = v0;
                *reinterpret_cast<float2*>(&Cf[(size_t)(mrow + 8) * Nn + ncol]) = v1;
            }
        }
        if (EPI == 3) {
            rs0 += __shfl_xor_sync(~0u, rs0, 1);
            rs0 += __shfl_xor_sync(~0u, rs0, 2);
            rs1 += __shfl_xor_sync(~0u, rs1, 1);
            rs1 += __shfl_xor_sync(~0u, rs1, 2);
            if (tig == 0) {
                atomicAdd(&rsum[mrow], rs0);
                atomicAdd(&rsum[mrow + 8], rs1);
            }
        }
    }
}

// Merged q/k projection (fp16): blockIdx.x selects Wq->q or Wk->k.
// N=128, K=1024. C = half(acc + bias[n]).
__global__ __launch_bounds__(256, 2)
void gemm_qk(const __half* __restrict__ A,
             const __half* __restrict__ B0, const __half* __restrict__ B1,
             const float* __restrict__ bias0, const float* __restrict__ bias1,
             __half* __restrict__ C0, __half* __restrict__ C1) {
    const int selk = blockIdx.x;
    const __half* Bsel = selk ? B1 : B0;
    const float* bias = selk ? bias1 : bias0;
    __half* C = selk ? C1 : C0;
    const int m0 = blockIdx.y * 128, n0 = 0;
    const int Nn = HDIM;
    GEMMH_PROLOG
    GEMMH_MAIN(A, Bsel, CDIM)

    const int g = lane >> 2, tig = lane & 3;
#pragma unroll
    for (int mt = 0; mt < 4; mt++) {
        const int mrow = m0 + wm * 64 + mt * 16 + g;
#pragma unroll
        for (int nt = 0; nt < 4; nt++) {
            const int ncol = wn * 32 + nt * 8 + tig * 2;
            float* cc = acc[mt][nt];
            float b0 = bias[ncol], b1 = bias[ncol + 1];
            *reinterpret_cast<__half2*>(&C[(size_t)mrow * Nn + ncol]) =
                __halves2half2(__float2half_rn(cc[0] + b0),
                               __float2half_rn(cc[1] + b1));
            *reinterpret_cast<__half2*>(&C[(size_t)(mrow + 8) * Nn + ncol]) =
                __halves2half2(__float2half_rn(cc[2] + b0),
                               __float2half_rn(cc[3] + b1));
        }
    }
}

// ---------------------------------------------------------------------------
extern "C" void kernel_launch(void* const* d_in, const int* in_sizes, int n_in,
                              void* d_out, int out_size) {
    const float* x  = (const float*)d_in[0];
    const float* Wq = (const float*)d_in[1];
    const float* bq = (const float*)d_in[2];
    const float* Wk = (const float*)d_in[3];
    const float* bk = (const float*)d_in[4];
    const float* Wv = (const float*)d_in[5];
    const float* bv = (const float*)d_in[6];
    const float* Wo = (const float*)d_in[7];
    const float* bo = (const float*)d_in[8];
    float* out = (float*)d_out;

    __half *xh, *wqh, *wkh, *wvh, *woh, *qh, *kh, *vTh, *sh, *oh;
    float *rs;
    cudaGetSymbolAddress((void**)&xh,  g_xh);
    cudaGetSymbolAddress((void**)&wqh, g_wqh);
    cudaGetSymbolAddress((void**)&wkh, g_wkh);
    cudaGetSymbolAddress((void**)&wvh, g_wvh);
    cudaGetSymbolAddress((void**)&woh, g_woh);
    cudaGetSymbolAddress((void**)&qh,  g_qh);
    cudaGetSymbolAddress((void**)&kh,  g_kh);
    cudaGetSymbolAddress((void**)&vTh, g_vTh);
    cudaGetSymbolAddress((void**)&sh,  g_sh);
    cudaGetSymbolAddress((void**)&oh,  g_oh);
    cudaGetSymbolAddress((void**)&rs,  g_rsum);

    const float scale = 1.0f / sqrtf((float)HDIM);
    const int SMEMH = NSTAGE * HBUFB;   // 81920

    cudaFuncSetAttribute(gemm_qk,    cudaFuncAttributeMaxDynamicSharedMemorySize, SMEMH);
    cudaFuncSetAttribute(gemm_h<3>,  cudaFuncAttributeMaxDynamicSharedMemorySize, SMEMH);
    cudaFuncSetAttribute(gemm_h<4>,  cudaFuncAttributeMaxDynamicSharedMemorySize, SMEMH);
    cudaFuncSetAttribute(gemm_h<5>,  cudaFuncAttributeMaxDynamicSharedMemorySize, SMEMH);
    cudaFuncSetAttribute(gemm_h<6>,  cudaFuncAttributeMaxDynamicSharedMemorySize, SMEMH);

    dim3 blk(256);

    // Side stream + events for capture fork/join. kernel_launch only runs a
    // couple of times (correctness + capture); replays re-execute the graph,
    // so per-call creation is safe and keeps the call deterministic.
    cudaStream_t s2;
    cudaStreamCreate(&s2);
    cudaEvent_t e0, eX, eVT, eWO;
    cudaEventCreateWithFlags(&e0,  cudaEventDisableTiming);
    cudaEventCreateWithFlags(&eX,  cudaEventDisableTiming);
    cudaEventCreateWithFlags(&eVT, cudaEventDisableTiming);
    cudaEventCreateWithFlags(&eWO, cudaEventDisableTiming);

    // Fork: make s2 capture-dependent on the main stream from the start.
    cudaEventRecord(e0, 0);
    cudaStreamWaitEvent(s2, e0, 0);

    // ---- main stream: x/Wq/Wk conversions, qk, scores ----
    f2h<<<(NTOK * CDIM / 4 + 255) / 256, blk>>>(x,  xh,  NTOK * CDIM / 4);
    cudaEventRecord(eX, 0);                      // x done -> vT may start
    f2h<<<(HDIM * CDIM / 4 + 255) / 256, blk>>>(Wq, wqh, HDIM * CDIM / 4);
    f2h<<<(HDIM * CDIM / 4 + 255) / 256, blk>>>(Wk, wkh, HDIM * CDIM / 4);
    zero_rsum<<<NTOK / 256, blk>>>(rs);

    // ---- side stream: Wv/Wo conversions + vT (independent of qk/scores) ----
    f2h<<<(CDIM * CDIM / 4 + 255) / 256, blk, 0, s2>>>(Wv, wvh, CDIM * CDIM / 4);
    cudaStreamWaitEvent(s2, eX, 0);
    gemm_h<6><<<dim3(64, 8), blk, SMEMH, s2>>>(wvh, xh, bv, nullptr, vTh,
                                               CDIM, NTOK, CDIM, 1.0f);
    cudaEventRecord(eVT, s2);
    f2h<<<(CDIM * CDIM / 4 + 255) / 256, blk, 0, s2>>>(Wo, woh, CDIM * CDIM / 4);
    cudaEventRecord(eWO, s2);

    // ---- main stream continues ----
    // q,k projections merged: grid (2, 64)
    gemm_qk<<<dim3(2, 64), blk, SMEMH>>>(xh, wqh, wkh, bq, bk, qh, kh);

    // P_hat = fp16(exp(scale * q@k.T)/16) + rsum atomics
    gemm_h<3><<<dim3(64, 64), blk, SMEMH>>>(qh, kh, nullptr, rs, sh,
                                            NTOK, NTOK, HDIM, scale);

    // Join: attn needs vT; out needs Wo.
    cudaStreamWaitEvent(0, eVT, 0);
    gemm_h<4><<<dim3(8, 64), blk, SMEMH>>>(sh, vTh, nullptr, rs, oh,
                                           NTOK, CDIM, NTOK, 1.0f);

    cudaStreamWaitEvent(0, eWO, 0);
    gemm_h<5><<<dim3(8, 64), blk, SMEMH>>>(oh, woh, bo, nullptr, out,
                                           NTOK, CDIM, CDIM, 1.0f);
}

// round 11
// speedup vs baseline: 2.1349x; 1.1204x over previous
#include <cuda_runtime.h>
#include <cuda_fp16.h>
#include <math.h>
#include <cstdint>

#define NTOK 8192
#define CDIM 1024
#define HDIM 128

// Scratch (__device__ globals; allocation-free rule)
__device__ __half g_xh [(size_t)NTOK * CDIM];   // fp16 x
__device__ __half g_wqh[(size_t)HDIM * CDIM];
__device__ __half g_wkh[(size_t)HDIM * CDIM];
__device__ __half g_wvh[(size_t)CDIM * CDIM];
__device__ __half g_woh[(size_t)CDIM * CDIM];
__device__ __half g_qh [(size_t)NTOK * HDIM];
__device__ __half g_kh [(size_t)NTOK * HDIM];
__device__ __half g_vTh[(size_t)CDIM * NTOK];   // v transposed, fp16
__device__ __half g_sh [(size_t)NTOK * NTOK];   // exp'd scores fp16 (scaled 1/16)
__device__ __half g_oh [(size_t)NTOK * CDIM];   // attn output, fp16
__device__ float  g_rsum[NTOK];                 // softmax row sums (scaled)

// ---------------- portable PTX helpers (sm_80-level only) ----------------
__device__ __forceinline__ uint32_t smem_u32(const void* p) {
    uint32_t a;
    asm("{ .reg .u64 t; cvta.to.shared.u64 t, %1; cvt.u32.u64 %0, t; }"
        : "=r"(a) : "l"(p));
    return a;
}
__device__ __forceinline__ void cp16(uint32_t s, const void* g) {
    asm volatile("cp.async.cg.shared.global [%0], [%1], 16;" :: "r"(s), "l"(g));
}
__device__ __forceinline__ void ldsm4(uint32_t& r0, uint32_t& r1,
                                      uint32_t& r2, uint32_t& r3, uint32_t a) {
    asm volatile("ldmatrix.sync.aligned.m8n8.x4.shared.b16 {%0,%1,%2,%3}, [%4];"
                 : "=r"(r0), "=r"(r1), "=r"(r2), "=r"(r3) : "r"(a));
}
__device__ __forceinline__ void mma16h(float* c, const uint32_t* a, const uint32_t* b) {
    asm volatile(
        "mma.sync.aligned.m16n8k16.row.col.f32.f16.f16.f32 "
        "{%0,%1,%2,%3}, {%4,%5,%6,%7}, {%8,%9}, {%0,%1,%2,%3};"
        : "+f"(c[0]), "+f"(c[1]), "+f"(c[2]), "+f"(c[3])
        : "r"(a[0]), "r"(a[1]), "r"(a[2]), "r"(a[3]), "r"(b[0]), "r"(b[1]));
}

// ---------------------------------------------------------------------------
__global__ __launch_bounds__(256)
void f2h(const float* __restrict__ src, __half* __restrict__ dst, int n4) {
    int i = blockIdx.x * 256 + threadIdx.x;
    if (i < n4) {
        float4 v = reinterpret_cast<const float4*>(src)[i];
        __half2 h0 = __halves2half2(__float2half_rn(v.x), __float2half_rn(v.y));
        __half2 h1 = __halves2half2(__float2half_rn(v.z), __float2half_rn(v.w));
        reinterpret_cast<__half2*>(dst)[i * 2]     = h0;
        reinterpret_cast<__half2*>(dst)[i * 2 + 1] = h1;
    }
}
__global__ __launch_bounds__(256)
void zero_rsum(float* __restrict__ r) {
    r[blockIdx.x * 256 + threadIdx.x] = 0.f;
}

// ===========================================================================
// fp16 tensor-core GEMM: C = A @ B^T (+epilogue), A:(M,K) B:(Nn,K) fp16 K-major.
// CTA 128x128, BK=64 halves (128 B), 3-stage cp.async multistage with a
// SINGLE barrier per iteration (CUTLASS pattern), 8 warps 2(M)x4(N),
// warp tile 64x32, mma.m16n8k16, fp32 accum, 2 CTAs/SM.
// Rows padded to 72 halves (144 B): (9r+c) mod 8 -> conflict-free ldmatrix.
// EPI: 3 = half(exp(acc*alpha)/16) -> half C, rsum atomics  (scores)
//      4 = half(acc / rsum[m])     -> half C                (attn@v)
//      5 = acc + bias[n]           -> float C               (final out-proj)
//      6 = half(acc + bias[m])     -> half C                (vT)
// ===========================================================================
#define HST 72                          // halves per padded row (144 B)
#define HTILEB (128 * HST * 2)          // 18432 B
#define HBUFB  (2 * HTILEB)             // 36864 B per stage
#define NSTAGE 3

#define GEMMH_PROLOG                                                            \
    extern __shared__ float sm[];                                               \
    const uint32_t sA = smem_u32(sm);                                           \
    const uint32_t sB = sA + HTILEB;                                            \
    const int tid = threadIdx.x;                                                \
    const int lane = tid & 31, wid = tid >> 5;                                  \
    const int wm = wid >> 2, wn = wid & 3;                                      \
    const int q = lane & 7, sub = lane >> 3;                                    \
    uint32_t aAddr[4], bAddr[2];                                                \
    _Pragma("unroll")                                                           \
    for (int mt = 0; mt < 4; mt++) {                                            \
        int row = wm * 64 + mt * 16 + (sub & 1) * 8 + q;                        \
        aAddr[mt] = sA + (uint32_t)(row * HST + (sub >> 1) * 8) * 2;            \
    }                                                                           \
    _Pragma("unroll")                                                           \
    for (int p = 0; p < 2; p++) {                                               \
        int row = wn * 32 + p * 16 + (sub >> 1) * 8 + q;                        \
        bAddr[p] = sB + (uint32_t)(row * HST + (sub & 1) * 8) * 2;              \
    }

// Single-barrier multistage mainloop.
// Prologue: stages 0..NSTAGE-2 in flight. Iter c: wait stage c, barrier,
// issue loads into slot (c-1) mod NSTAGE (consumed last iter), compute c.
#define GEMMH_MAIN(Aptr, Bptr, Kdim)                                            \
    const int NC = (Kdim) >> 6;                                                 \
    auto load = [&](int c, int b) {                                             \
        if (c < NC) {                                                           \
            const uint32_t aBase = sA + (uint32_t)b * HBUFB;                    \
            const uint32_t bBase = sB + (uint32_t)b * HBUFB;                    \
            _Pragma("unroll")                                                   \
            for (int it = 0; it < 8; it++) {                                    \
                int i = tid + it * 256;                                         \
                bool isA = i < 1024;                                            \
                int idx = i & 1023;                                             \
                int rr = idx >> 3, cc = idx & 7;                                \
                const __half* g = (isA ? (Aptr) : (Bptr)) +                     \
                    (size_t)((isA ? m0 : n0) + rr) * (Kdim) + c * 64 + cc * 8;  \
                cp16((isA ? aBase : bBase) + (uint32_t)(rr * HST + cc * 8) * 2, g); \
            }                                                                   \
        }                                                                       \
        asm volatile("cp.async.commit_group;" ::: "memory");                    \
    };                                                                          \
    _Pragma("unroll")                                                           \
    for (int s = 0; s < NSTAGE - 1; s++) load(s, s);                            \
    float acc[4][4][4];                                                         \
    _Pragma("unroll")                                                           \
    for (int i = 0; i < 4; i++)                                                 \
        _Pragma("unroll")                                                       \
        for (int j = 0; j < 4; j++)                                             \
            _Pragma("unroll")                                                   \
            for (int r = 0; r < 4; r++) acc[i][j][r] = 0.f;                     \
    for (int c = 0; c < NC; c++) {                                              \
        asm volatile("cp.async.wait_group %0;" :: "n"(NSTAGE - 2) : "memory");  \
        __syncthreads();                                                        \
        load(c + NSTAGE - 1, (c + NSTAGE - 1) % NSTAGE);                        \
        const uint32_t boff = (uint32_t)(c % NSTAGE) * HBUFB;                   \
        _Pragma("unroll")                                                       \
        for (int ks = 0; ks < 4; ks++) {                                        \
            uint32_t af[4][4], bf[4][2];                                        \
            _Pragma("unroll")                                                   \
            for (int mt = 0; mt < 4; mt++)                                      \
                ldsm4(af[mt][0], af[mt][1], af[mt][2], af[mt][3],               \
                      aAddr[mt] + boff + ks * 32);                              \
            _Pragma("unroll")                                                   \
            for (int p = 0; p < 2; p++) {                                       \
                uint32_t r0, r1, r2, r3;                                        \
                ldsm4(r0, r1, r2, r3, bAddr[p] + boff + ks * 32);               \
                bf[p * 2][0] = r0; bf[p * 2][1] = r1;                           \
                bf[p * 2 + 1][0] = r2; bf[p * 2 + 1][1] = r3;                   \
            }                                                                   \
            _Pragma("unroll")                                                   \
            for (int mt = 0; mt < 4; mt++)                                      \
                _Pragma("unroll")                                               \
                for (int nt = 0; nt < 4; nt++)                                  \
                    mma16h(acc[mt][nt], af[mt], bf[nt]);                        \
        }                                                                       \
    }

template <int EPI>
__global__ __launch_bounds__(256, 2)
void gemm_h(const __half* __restrict__ A, const __half* __restrict__ B,
            const float* __restrict__ bias, float* __restrict__ rsum,
            void* __restrict__ Cv, int M, int Nn, int K, float alpha) {
    const int m0 = blockIdx.y * 128, n0 = blockIdx.x * 128;
    GEMMH_PROLOG
    GEMMH_MAIN(A, B, K)

    float* Cf = (float*)Cv;
    __half* Ch = (__half*)Cv;
    const int g = lane >> 2, tig = lane & 3;
#pragma unroll
    for (int mt = 0; mt < 4; mt++) {
        const int mrow = m0 + wm * 64 + mt * 16 + g;
        float bR0 = 0.f, bR1 = 0.f;
        if (EPI == 6) { bR0 = bias[mrow]; bR1 = bias[mrow + 8]; }
        if (EPI == 4) { bR0 = 1.0f / rsum[mrow]; bR1 = 1.0f / rsum[mrow + 8]; }
        float rs0 = 0.f, rs1 = 0.f;
#pragma unroll
        for (int nt = 0; nt < 4; nt++) {
            const int ncol = n0 + wn * 32 + nt * 8 + tig * 2;
            float* cc = acc[mt][nt];
            if (EPI == 3) {
                __half h0 = __float2half_rn(__expf(cc[0] * alpha) * 0.0625f);
                __half h1 = __float2half_rn(__expf(cc[1] * alpha) * 0.0625f);
                __half h2 = __float2half_rn(__expf(cc[2] * alpha) * 0.0625f);
                __half h3 = __float2half_rn(__expf(cc[3] * alpha) * 0.0625f);
                rs0 += __half2float(h0) + __half2float(h1);
                rs1 += __half2float(h2) + __half2float(h3);
                *reinterpret_cast<__half2*>(&Ch[(size_t)mrow * Nn + ncol]) =
                    __halves2half2(h0, h1);
                *reinterpret_cast<__half2*>(&Ch[(size_t)(mrow + 8) * Nn + ncol]) =
                    __halves2half2(h2, h3);
            } else if (EPI == 4) {
                *reinterpret_cast<__half2*>(&Ch[(size_t)mrow * Nn + ncol]) =
                    __halves2half2(__float2half_rn(cc[0] * bR0),
                                   __float2half_rn(cc[1] * bR0));
                *reinterpret_cast<__half2*>(&Ch[(size_t)(mrow + 8) * Nn + ncol]) =
                    __halves2half2(__float2half_rn(cc[2] * bR1),
                                   __float2half_rn(cc[3] * bR1));
            } else if (EPI == 6) {
                *reinterpret_cast<__half2*>(&Ch[(size_t)mrow * Nn + ncol]) =
                    __halves2half2(__float2half_rn(cc[0] + bR0),
                                   __float2half_rn(cc[1] + bR0));
                *reinterpret_cast<__half2*>(&Ch[(size_t)(mrow + 8) * Nn + ncol]) =
                    __halves2half2(__float2half_rn(cc[2] + bR1),
                                   __float2half_rn(cc[3] + bR1));
            } else {  // EPI == 5: final, float out + bias[n]
                float b0 = bias[ncol], b1 = bias[ncol + 1];
                float2 v0 = {cc[0] + b0, cc[1] + b1};
                float2 v1 = {cc[2] + b0, cc[3] + b1};
                *reinterpret_cast<float2*>(&Cf[(size_t)mrow * Nn + ncol]) = v0;
                *reinterpret_cast<float2*>(&Cf[(size_t)(mrow + 8) * Nn + ncol]) = v1;
            }
        }
        if (EPI == 3) {
            rs0 += __shfl_xor_sync(~0u, rs0, 1);
            rs0 += __shfl_xor_sync(~0u, rs0, 2);
            rs1 += __shfl_xor_sync(~0u, rs1, 1);
            rs1 += __shfl_xor_sync(~0u, rs1, 2);
            if (tig == 0) {
                atomicAdd(&rsum[mrow], rs0);
                atomicAdd(&rsum[mrow + 8], rs1);
            }
        }
    }
}

// Merged q/k projection (fp16): blockIdx.x selects Wq->q or Wk->k.
// N=128, K=1024. C = half(acc + bias[n]).
__global__ __launch_bounds__(256, 2)
void gemm_qk(const __half* __restrict__ A,
             const __half* __restrict__ B0, const __half* __restrict__ B1,
             const float* __restrict__ bias0, const float* __restrict__ bias1,
             __half* __restrict__ C0, __half* __restrict__ C1) {
    const int selk = blockIdx.x;
    const __half* Bsel = selk ? B1 : B0;
    const float* bias = selk ? bias1 : bias0;
    __half* C = selk ? C1 : C0;
    const int m0 = blockIdx.y * 128, n0 = 0;
    const int Nn = HDIM;
    GEMMH_PROLOG
    GEMMH_MAIN(A, Bsel, CDIM)

    const int g = lane >> 2, tig = lane & 3;
#pragma unroll
    for (int mt = 0; mt < 4; mt++) {
        const int mrow = m0 + wm * 64 + mt * 16 + g;
#pragma unroll
        for (int nt = 0; nt < 4; nt++) {
            const int ncol = wn * 32 + nt * 8 + tig * 2;
            float* cc = acc[mt][nt];
            float b0 = bias[ncol], b1 = bias[ncol + 1];
            *reinterpret_cast<__half2*>(&C[(size_t)mrow * Nn + ncol]) =
                __halves2half2(__float2half_rn(cc[0] + b0),
                               __float2half_rn(cc[1] + b1));
            *reinterpret_cast<__half2*>(&C[(size_t)(mrow + 8) * Nn + ncol]) =
                __halves2half2(__float2half_rn(cc[2] + b0),
                               __float2half_rn(cc[3] + b1));
        }
    }
}

// ---------------------------------------------------------------------------
extern "C" void kernel_launch(void* const* d_in, const int* in_sizes, int n_in,
                              void* d_out, int out_size) {
    const float* x  = (const float*)d_in[0];
    const float* Wq = (const float*)d_in[1];
    const float* bq = (const float*)d_in[2];
    const float* Wk = (const float*)d_in[3];
    const float* bk = (const float*)d_in[4];
    const float* Wv = (const float*)d_in[5];
    const float* bv = (const float*)d_in[6];
    const float* Wo = (const float*)d_in[7];
    const float* bo = (const float*)d_in[8];
    float* out = (float*)d_out;

    __half *xh, *wqh, *wkh, *wvh, *woh, *qh, *kh, *vTh, *sh, *oh;
    float *rs;
    cudaGetSymbolAddress((void**)&xh,  g_xh);
    cudaGetSymbolAddress((void**)&wqh, g_wqh);
    cudaGetSymbolAddress((void**)&wkh, g_wkh);
    cudaGetSymbolAddress((void**)&wvh, g_wvh);
    cudaGetSymbolAddress((void**)&woh, g_woh);
    cudaGetSymbolAddress((void**)&qh,  g_qh);
    cudaGetSymbolAddress((void**)&kh,  g_kh);
    cudaGetSymbolAddress((void**)&vTh, g_vTh);
    cudaGetSymbolAddress((void**)&sh,  g_sh);
    cudaGetSymbolAddress((void**)&oh,  g_oh);
    cudaGetSymbolAddress((void**)&rs,  g_rsum);

    const float scale = 1.0f / sqrtf((float)HDIM);
    const int SMEMH = NSTAGE * HBUFB;   // 110592

    cudaFuncSetAttribute(gemm_qk,    cudaFuncAttributeMaxDynamicSharedMemorySize, SMEMH);
    cudaFuncSetAttribute(gemm_h<3>,  cudaFuncAttributeMaxDynamicSharedMemorySize, SMEMH);
    cudaFuncSetAttribute(gemm_h<4>,  cudaFuncAttributeMaxDynamicSharedMemorySize, SMEMH);
    cudaFuncSetAttribute(gemm_h<5>,  cudaFuncAttributeMaxDynamicSharedMemorySize, SMEMH);
    cudaFuncSetAttribute(gemm_h<6>,  cudaFuncAttributeMaxDynamicSharedMemorySize, SMEMH);

    dim3 blk(256);

    // Side stream + events for capture fork/join (per-call creation is safe;
    // only correctness + capture invoke this function).
    cudaStream_t s2;
    cudaStreamCreate(&s2);
    cudaEvent_t e0, eX, eVT, eWO;
    cudaEventCreateWithFlags(&e0,  cudaEventDisableTiming);
    cudaEventCreateWithFlags(&eX,  cudaEventDisableTiming);
    cudaEventCreateWithFlags(&eVT, cudaEventDisableTiming);
    cudaEventCreateWithFlags(&eWO, cudaEventDisableTiming);

    cudaEventRecord(e0, 0);
    cudaStreamWaitEvent(s2, e0, 0);

    // ---- main stream: x/Wq/Wk conversions, qk, scores ----
    f2h<<<(NTOK * CDIM / 4 + 255) / 256, blk>>>(x,  xh,  NTOK * CDIM / 4);
    cudaEventRecord(eX, 0);
    f2h<<<(HDIM * CDIM / 4 + 255) / 256, blk>>>(Wq, wqh, HDIM * CDIM / 4);
    f2h<<<(HDIM * CDIM / 4 + 255) / 256, blk>>>(Wk, wkh, HDIM * CDIM / 4);
    zero_rsum<<<NTOK / 256, blk>>>(rs);

    // ---- side stream: Wv/Wo conversions + vT ----
    f2h<<<(CDIM * CDIM / 4 + 255) / 256, blk, 0, s2>>>(Wv, wvh, CDIM * CDIM / 4);
    cudaStreamWaitEvent(s2, eX, 0);
    gemm_h<6><<<dim3(64, 8), blk, SMEMH, s2>>>(wvh, xh, bv, nullptr, vTh,
                                               CDIM, NTOK, CDIM, 1.0f);
    cudaEventRecord(eVT, s2);
    f2h<<<(CDIM * CDIM / 4 + 255) / 256, blk, 0, s2>>>(Wo, woh, CDIM * CDIM / 4);
    cudaEventRecord(eWO, s2);

    // ---- main stream continues ----
    gemm_qk<<<dim3(2, 64), blk, SMEMH>>>(xh, wqh, wkh, bq, bk, qh, kh);

    gemm_h<3><<<dim3(64, 64), blk, SMEMH>>>(qh, kh, nullptr, rs, sh,
                                            NTOK, NTOK, HDIM, scale);

    cudaStreamWaitEvent(0, eVT, 0);
    gemm_h<4><<<dim3(8, 64), blk, SMEMH>>>(sh, vTh, nullptr, rs, oh,
                                           NTOK, CDIM, NTOK, 1.0f);

    cudaStreamWaitEvent(0, eWO, 0);
    gemm_h<5><<<dim3(8, 64), blk, SMEMH>>>(oh, woh, bo, nullptr, out,
                                           NTOK, CDIM, CDIM, 1.0f);
}

// round 12
// speedup vs baseline: 2.3277x; 1.0903x over previous
#include <cuda_runtime.h>
#include <cuda_fp16.h>
#include <math.h>
#include <cstdint>

#define NTOK 8192
#define CDIM 1024
#define HDIM 128

// Scratch (__device__ globals; allocation-free rule)
__device__ __half g_xh  [(size_t)NTOK * CDIM];   // fp16 x
__device__ __half g_wqh [(size_t)HDIM * CDIM];
__device__ __half g_wkh [(size_t)HDIM * CDIM];
__device__ __half g_woh [(size_t)CDIM * CDIM];   // fp16 Wo
__device__ __half g_wvtT[(size_t)CDIM * CDIM];   // fp16 Wv TRANSPOSED (WvT[n,k]=Wv[k,n])
__device__ __half g_w2h [(size_t)CDIM * CDIM];   // W' = Wo @ Wv, fp16
__device__ __half g_qh  [(size_t)NTOK * HDIM];
__device__ __half g_kh  [(size_t)NTOK * HDIM];
__device__ __half g_vTh [(size_t)CDIM * NTOK];   // vfused transposed, fp16
__device__ __half g_sh  [(size_t)NTOK * NTOK];   // exp'd scores fp16 (scaled 1/16)
__device__ float  g_rsum[NTOK];                  // softmax row sums (scaled)
__device__ float  g_bp  [CDIM];                  // b' = Wo@bv + bo

// ---------------- portable PTX helpers (sm_80-level only) ----------------
__device__ __forceinline__ uint32_t smem_u32(const void* p) {
    uint32_t a;
    asm("{ .reg .u64 t; cvta.to.shared.u64 t, %1; cvt.u32.u64 %0, t; }"
        : "=r"(a) : "l"(p));
    return a;
}
__device__ __forceinline__ void cp16(uint32_t s, const void* g) {
    asm volatile("cp.async.cg.shared.global [%0], [%1], 16;" :: "r"(s), "l"(g));
}
__device__ __forceinline__ void ldsm4(uint32_t& r0, uint32_t& r1,
                                      uint32_t& r2, uint32_t& r3, uint32_t a) {
    asm volatile("ldmatrix.sync.aligned.m8n8.x4.shared.b16 {%0,%1,%2,%3}, [%4];"
                 : "=r"(r0), "=r"(r1), "=r"(r2), "=r"(r3) : "r"(a));
}
__device__ __forceinline__ void mma16h(float* c, const uint32_t* a, const uint32_t* b) {
    asm volatile(
        "mma.sync.aligned.m16n8k16.row.col.f32.f16.f16.f32 "
        "{%0,%1,%2,%3}, {%4,%5,%6,%7}, {%8,%9}, {%0,%1,%2,%3};"
        : "+f"(c[0]), "+f"(c[1]), "+f"(c[2]), "+f"(c[3])
        : "r"(a[0]), "r"(a[1]), "r"(a[2]), "r"(a[3]), "r"(b[0]), "r"(b[1]));
}

// ---------------------------------------------------------------------------
__global__ __launch_bounds__(256)
void f2h(const float* __restrict__ src, __half* __restrict__ dst, int n4) {
    int i = blockIdx.x * 256 + threadIdx.x;
    if (i < n4) {
        float4 v = reinterpret_cast<const float4*>(src)[i];
        reinterpret_cast<__half2*>(dst)[i * 2] =
            __halves2half2(__float2half_rn(v.x), __float2half_rn(v.y));
        reinterpret_cast<__half2*>(dst)[i * 2 + 1] =
            __halves2half2(__float2half_rn(v.z), __float2half_rn(v.w));
    }
}
// Transpose 1024x1024 float -> fp16 (dst[n,k] = src[k,n])
__global__ __launch_bounds__(256)
void f2h_t(const float* __restrict__ src, __half* __restrict__ dst) {
    __shared__ float t[32][33];
    const int bx = blockIdx.x * 32, by = blockIdx.y * 32;
    const int tx = threadIdx.x & 31, ty = threadIdx.x >> 5;   // 32 x 8
#pragma unroll
    for (int j = 0; j < 32; j += 8)
        t[ty + j][tx] = src[(size_t)(by + ty + j) * CDIM + bx + tx];
    __syncthreads();
#pragma unroll
    for (int j = 0; j < 32; j += 8)
        dst[(size_t)(bx + ty + j) * CDIM + by + tx] =
            __float2half_rn(t[tx][ty + j]);
}
__global__ __launch_bounds__(256)
void zero_rsum(float* __restrict__ r) {
    r[blockIdx.x * 256 + threadIdx.x] = 0.f;
}
// b'[i] = sum_k Wo[i,k]*bv[k] + bo[i]. One block (128 thr) per output row.
__global__ __launch_bounds__(128)
void bprime_k(const float* __restrict__ Wo, const float* __restrict__ bv,
              const float* __restrict__ bo, float* __restrict__ bp) {
    const int i = blockIdx.x;
    const int tid = threadIdx.x;
    float s = 0.f;
    for (int k = tid; k < CDIM; k += 128)
        s += Wo[(size_t)i * CDIM + k] * bv[k];
#pragma unroll
    for (int o = 16; o > 0; o >>= 1) s += __shfl_xor_sync(~0u, s, o);
    __shared__ float red[4];
    if ((tid & 31) == 0) red[tid >> 5] = s;
    __syncthreads();
    if (tid == 0) bp[i] = red[0] + red[1] + red[2] + red[3] + bo[i];
}

// ===========================================================================
// fp16 tensor-core GEMM: C = A @ B^T (+epilogue), A:(M,K) B:(Nn,K) fp16 K-major.
// CTA 128x128, BK=64 halves, 3-stage single-barrier multistage, 8 warps
// 2(M)x4(N), warp tile 64x32, mma.m16n8k16, fp32 accum, 2 CTAs/SM.
// Rows padded to 72 halves (144 B) -> conflict-free ldmatrix.
// EPI: 3 = half(exp(acc*alpha)/16) -> half C, rsum atomics  (scores)
//      7 = half(acc)               -> half C                (W', vfused)
//      8 = acc/rsum[m] + bias[n]   -> float C               (fused attn+out)
// ===========================================================================
#define HST 72
#define HTILEB (128 * HST * 2)
#define HBUFB  (2 * HTILEB)
#define NSTAGE 3

#define GEMMH_PROLOG                                                            \
    extern __shared__ float sm[];                                               \
    const uint32_t sA = smem_u32(sm);                                           \
    const uint32_t sB = sA + HTILEB;                                            \
    const int tid = threadIdx.x;                                                \
    const int lane = tid & 31, wid = tid >> 5;                                  \
    const int wm = wid >> 2, wn = wid & 3;                                      \
    const int q = lane & 7, sub = lane >> 3;                                    \
    uint32_t aAddr[4], bAddr[2];                                                \
    _Pragma("unroll")                                                           \
    for (int mt = 0; mt < 4; mt++) {                                            \
        int row = wm * 64 + mt * 16 + (sub & 1) * 8 + q;                        \
        aAddr[mt] = sA + (uint32_t)(row * HST + (sub >> 1) * 8) * 2;            \
    }                                                                           \
    _Pragma("unroll")                                                           \
    for (int p = 0; p < 2; p++) {                                               \
        int row = wn * 32 + p * 16 + (sub >> 1) * 8 + q;                        \
        bAddr[p] = sB + (uint32_t)(row * HST + (sub & 1) * 8) * 2;              \
    }

#define GEMMH_MAIN(Aptr, Bptr, Kdim)                                            \
    const int NC = (Kdim) >> 6;                                                 \
    auto load = [&](int c, int b) {                                             \
        if (c < NC) {                                                           \
            const uint32_t aBase = sA + (uint32_t)b * HBUFB;                    \
            const uint32_t bBase = sB + (uint32_t)b * HBUFB;                    \
            _Pragma("unroll")                                                   \
            for (int it = 0; it < 8; it++) {                                    \
                int i = tid + it * 256;                                         \
                bool isA = i < 1024;                                            \
                int idx = i & 1023;                                             \
                int rr = idx >> 3, cc = idx & 7;                                \
                const __half* g = (isA ? (Aptr) : (Bptr)) +                     \
                    (size_t)((isA ? m0 : n0) + rr) * (Kdim) + c * 64 + cc * 8;  \
                cp16((isA ? aBase : bBase) + (uint32_t)(rr * HST + cc * 8) * 2, g); \
            }                                                                   \
        }                                                                       \
        asm volatile("cp.async.commit_group;" ::: "memory");                    \
    };                                                                          \
    _Pragma("unroll")                                                           \
    for (int s = 0; s < NSTAGE - 1; s++) load(s, s);                            \
    float acc[4][4][4];                                                         \
    _Pragma("unroll")                                                           \
    for (int i = 0; i < 4; i++)                                                 \
        _Pragma("unroll")                                                       \
        for (int j = 0; j < 4; j++)                                             \
            _Pragma("unroll")                                                   \
            for (int r = 0; r < 4; r++) acc[i][j][r] = 0.f;                     \
    for (int c = 0; c < NC; c++) {                                              \
        asm volatile("cp.async.wait_group %0;" :: "n"(NSTAGE - 2) : "memory");  \
        __syncthreads();                                                        \
        load(c + NSTAGE - 1, (c + NSTAGE - 1) % NSTAGE);                        \
        const uint32_t boff = (uint32_t)(c % NSTAGE) * HBUFB;                   \
        _Pragma("unroll")                                                       \
        for (int ks = 0; ks < 4; ks++) {                                        \
            uint32_t af[4][4], bf[4][2];                                        \
            _Pragma("unroll")                                                   \
            for (int mt = 0; mt < 4; mt++)                                      \
                ldsm4(af[mt][0], af[mt][1], af[mt][2], af[mt][3],               \
                      aAddr[mt] + boff + ks * 32);                              \
            _Pragma("unroll")                                                   \
            for (int p = 0; p < 2; p++) {                                       \
                uint32_t r0, r1, r2, r3;                                        \
                ldsm4(r0, r1, r2, r3, bAddr[p] + boff + ks * 32);               \
                bf[p * 2][0] = r0; bf[p * 2][1] = r1;                           \
                bf[p * 2 + 1][0] = r2; bf[p * 2 + 1][1] = r3;                   \
            }                                                                   \
            _Pragma("unroll")                                                   \
            for (int mt = 0; mt < 4; mt++)                                      \
                _Pragma("unroll")                                               \
                for (int nt = 0; nt < 4; nt++)                                  \
                    mma16h(acc[mt][nt], af[mt], bf[nt]);                        \
        }                                                                       \
    }

template <int EPI>
__global__ __launch_bounds__(256, 2)
void gemm_h(const __half* __restrict__ A, const __half* __restrict__ B,
            const float* __restrict__ bias, float* __restrict__ rsum,
            void* __restrict__ Cv, int M, int Nn, int K, float alpha) {
    const int m0 = blockIdx.y * 128, n0 = blockIdx.x * 128;
    GEMMH_PROLOG
    GEMMH_MAIN(A, B, K)

    float* Cf = (float*)Cv;
    __half* Ch = (__half*)Cv;
    const int g = lane >> 2, tig = lane & 3;
#pragma unroll
    for (int mt = 0; mt < 4; mt++) {
        const int mrow = m0 + wm * 64 + mt * 16 + g;
        float bR0 = 0.f, bR1 = 0.f;
        if (EPI == 8) { bR0 = 1.0f / rsum[mrow]; bR1 = 1.0f / rsum[mrow + 8]; }
        float rs0 = 0.f, rs1 = 0.f;
#pragma unroll
        for (int nt = 0; nt < 4; nt++) {
            const int ncol = n0 + wn * 32 + nt * 8 + tig * 2;
            float* cc = acc[mt][nt];
            if (EPI == 3) {
                __half h0 = __float2half_rn(__expf(cc[0] * alpha) * 0.0625f);
                __half h1 = __float2half_rn(__expf(cc[1] * alpha) * 0.0625f);
                __half h2 = __float2half_rn(__expf(cc[2] * alpha) * 0.0625f);
                __half h3 = __float2half_rn(__expf(cc[3] * alpha) * 0.0625f);
                rs0 += __half2float(h0) + __half2float(h1);
                rs1 += __half2float(h2) + __half2float(h3);
                *reinterpret_cast<__half2*>(&Ch[(size_t)mrow * Nn + ncol]) =
                    __halves2half2(h0, h1);
                *reinterpret_cast<__half2*>(&Ch[(size_t)(mrow + 8) * Nn + ncol]) =
                    __halves2half2(h2, h3);
            } else if (EPI == 7) {
                *reinterpret_cast<__half2*>(&Ch[(size_t)mrow * Nn + ncol]) =
                    __halves2half2(__float2half_rn(cc[0]),
                                   __float2half_rn(cc[1]));
                *reinterpret_cast<__half2*>(&Ch[(size_t)(mrow + 8) * Nn + ncol]) =
                    __halves2half2(__float2half_rn(cc[2]),
                                   __float2half_rn(cc[3]));
            } else {  // EPI == 8: out = acc/rsum + b'[n], float
                float b0 = bias[ncol], b1 = bias[ncol + 1];
                float2 v0 = {cc[0] * bR0 + b0, cc[1] * bR0 + b1};
                float2 v1 = {cc[2] * bR1 + b0, cc[3] * bR1 + b1};
                *reinterpret_cast<float2*>(&Cf[(size_t)mrow * Nn + ncol]) = v0;
                *reinterpret_cast<float2*>(&Cf[(size_t)(mrow + 8) * Nn + ncol]) = v1;
            }
        }
        if (EPI == 3) {
            rs0 += __shfl_xor_sync(~0u, rs0, 1);
            rs0 += __shfl_xor_sync(~0u, rs0, 2);
            rs1 += __shfl_xor_sync(~0u, rs1, 1);
            rs1 += __shfl_xor_sync(~0u, rs1, 2);
            if (tig == 0) {
                atomicAdd(&rsum[mrow], rs0);
                atomicAdd(&rsum[mrow + 8], rs1);
            }
        }
    }
}

// Merged q/k projection (fp16): blockIdx.x selects Wq->q or Wk->k.
__global__ __launch_bounds__(256, 2)
void gemm_qk(const __half* __restrict__ A,
             const __half* __restrict__ B0, const __half* __restrict__ B1,
             const float* __restrict__ bias0, const float* __restrict__ bias1,
             __half* __restrict__ C0, __half* __restrict__ C1) {
    const int selk = blockIdx.x;
    const __half* Bsel = selk ? B1 : B0;
    const float* bias = selk ? bias1 : bias0;
    __half* C = selk ? C1 : C0;
    const int m0 = blockIdx.y * 128, n0 = 0;
    const int Nn = HDIM;
    GEMMH_PROLOG
    GEMMH_MAIN(A, Bsel, CDIM)

    const int g = lane >> 2, tig = lane & 3;
#pragma unroll
    for (int mt = 0; mt < 4; mt++) {
        const int mrow = m0 + wm * 64 + mt * 16 + g;
#pragma unroll
        for (int nt = 0; nt < 4; nt++) {
            const int ncol = wn * 32 + nt * 8 + tig * 2;
            float* cc = acc[mt][nt];
            float b0 = bias[ncol], b1 = bias[ncol + 1];
            *reinterpret_cast<__half2*>(&C[(size_t)mrow * Nn + ncol]) =
                __halves2half2(__float2half_rn(cc[0] + b0),
                               __float2half_rn(cc[1] + b1));
            *reinterpret_cast<__half2*>(&C[(size_t)(mrow + 8) * Nn + ncol]) =
                __halves2half2(__float2half_rn(cc[2] + b0),
                               __float2half_rn(cc[3] + b1));
        }
    }
}

// ---------------------------------------------------------------------------
extern "C" void kernel_launch(void* const* d_in, const int* in_sizes, int n_in,
                              void* d_out, int out_size) {
    const float* x  = (const float*)d_in[0];
    const float* Wq = (const float*)d_in[1];
    const float* bq = (const float*)d_in[2];
    const float* Wk = (const float*)d_in[3];
    const float* bk = (const float*)d_in[4];
    const float* Wv = (const float*)d_in[5];
    const float* bv = (const float*)d_in[6];
    const float* Wo = (const float*)d_in[7];
    const float* bo = (const float*)d_in[8];
    float* out = (float*)d_out;

    __half *xh, *wqh, *wkh, *woh, *wvtT, *w2h, *qh, *kh, *vTh, *sh;
    float *rs, *bp;
    cudaGetSymbolAddress((void**)&xh,   g_xh);
    cudaGetSymbolAddress((void**)&wqh,  g_wqh);
    cudaGetSymbolAddress((void**)&wkh,  g_wkh);
    cudaGetSymbolAddress((void**)&woh,  g_woh);
    cudaGetSymbolAddress((void**)&wvtT, g_wvtT);
    cudaGetSymbolAddress((void**)&w2h,  g_w2h);
    cudaGetSymbolAddress((void**)&qh,   g_qh);
    cudaGetSymbolAddress((void**)&kh,   g_kh);
    cudaGetSymbolAddress((void**)&vTh,  g_vTh);
    cudaGetSymbolAddress((void**)&sh,   g_sh);
    cudaGetSymbolAddress((void**)&rs,   g_rsum);
    cudaGetSymbolAddress((void**)&bp,   g_bp);

    const float scale = 1.0f / sqrtf((float)HDIM);
    const int SMEMH = NSTAGE * HBUFB;   // 110592

    cudaFuncSetAttribute(gemm_qk,   cudaFuncAttributeMaxDynamicSharedMemorySize, SMEMH);
    cudaFuncSetAttribute(gemm_h<3>, cudaFuncAttributeMaxDynamicSharedMemorySize, SMEMH);
    cudaFuncSetAttribute(gemm_h<7>, cudaFuncAttributeMaxDynamicSharedMemorySize, SMEMH);
    cudaFuncSetAttribute(gemm_h<8>, cudaFuncAttributeMaxDynamicSharedMemorySize, SMEMH);

    dim3 blk(256);

    // Side stream + events (per-call creation is fine: only correctness +
    // capture invoke this function; replays re-run the captured graph).
    cudaStream_t s2;
    cudaStreamCreate(&s2);
    cudaEvent_t e0, eX, eVT;
    cudaEventCreateWithFlags(&e0,  cudaEventDisableTiming);
    cudaEventCreateWithFlags(&eX,  cudaEventDisableTiming);
    cudaEventCreateWithFlags(&eVT, cudaEventDisableTiming);

    cudaEventRecord(e0, 0);
    cudaStreamWaitEvent(s2, e0, 0);

    // ---- main stream: x/Wq/Wk conversions, qk, scores ----
    f2h<<<(NTOK * CDIM / 4 + 255) / 256, blk>>>(x,  xh,  NTOK * CDIM / 4);
    cudaEventRecord(eX, 0);
    f2h<<<(HDIM * CDIM / 4 + 255) / 256, blk>>>(Wq, wqh, HDIM * CDIM / 4);
    f2h<<<(HDIM * CDIM / 4 + 255) / 256, blk>>>(Wk, wkh, HDIM * CDIM / 4);
    zero_rsum<<<NTOK / 256, blk>>>(rs);

    // ---- side stream: W' = Wo@Wv, b', vfused = W'@x.T ----
    f2h<<<(CDIM * CDIM / 4 + 255) / 256, blk, 0, s2>>>(Wo, woh, CDIM * CDIM / 4);
    f2h_t<<<dim3(32, 32), blk, 0, s2>>>(Wv, wvtT);
    bprime_k<<<CDIM, 128, 0, s2>>>(Wo, bv, bo, bp);
    // W'[m,n] = sum_k Wo[m,k] * WvT[n,k] = (Wo @ Wv)[m,n]
    gemm_h<7><<<dim3(8, 8), blk, SMEMH, s2>>>(woh, wvtT, nullptr, nullptr, w2h,
                                              CDIM, CDIM, CDIM, 1.0f);
    cudaStreamWaitEvent(s2, eX, 0);
    // vfused^T = W' @ x^T   (M=CDIM rows = channels, N=NTOK tokens)
    gemm_h<7><<<dim3(64, 8), blk, SMEMH, s2>>>(w2h, xh, nullptr, nullptr, vTh,
                                               CDIM, NTOK, CDIM, 1.0f);
    cudaEventRecord(eVT, s2);

    // ---- main stream continues ----
    gemm_qk<<<dim3(2, 64), blk, SMEMH>>>(xh, wqh, wkh, bq, bk, qh, kh);

    // P_hat = fp16(exp(scale * q@k.T)/16) + rsum atomics
    gemm_h<3><<<dim3(64, 64), blk, SMEMH>>>(qh, kh, nullptr, rs, sh,
                                            NTOK, NTOK, HDIM, scale);

    // Join and finish: out = (P_hat @ vfused^T.T)/rsum + b'
    cudaStreamWaitEvent(0, eVT, 0);
    gemm_h<8><<<dim3(8, 64), blk, SMEMH>>>(sh, vTh, bp, rs, out,
                                           NTOK, CDIM, NTOK, 1.0f);
}